// round 9
// baseline (speedup 1.0000x reference)
#include <cuda_runtime.h>
#include <cuda_bf16.h>
#include <math.h>
#include <stdint.h>

#define B_ 32
#define N_ 1024
typedef __nv_bfloat16 bf16;

// ---------------- scratch (static device memory; no runtime alloc) ----------------
__device__ __align__(256) float g_A  [(size_t)B_*N_*N_];     // adjacency fp32
__device__ __align__(256) bf16  g_Lh [(size_t)B_*N_*N_];     // Laplacian hi
__device__ __align__(256) bf16  g_Ll [(size_t)B_*N_*N_];     // Laplacian lo
__device__ __align__(256) bf16  g_Xh [(size_t)B_*N_*512];    // layer input split (ping)
__device__ __align__(256) bf16  g_Xl [(size_t)B_*N_*512];
__device__ __align__(256) bf16  g_Yh [(size_t)B_*N_*512];    // layer input split (pong)
__device__ __align__(256) bf16  g_Yl [(size_t)B_*N_*512];
__device__ __align__(256) bf16  g_Th [(size_t)B_*512*N_];    // transposed operand split
__device__ __align__(256) bf16  g_Tl [(size_t)B_*512*N_];
__device__ __align__(256) float g_x1 [(size_t)B_*N_*512];
__device__ __align__(256) bf16  g_x1h[(size_t)B_*N_*512];
__device__ __align__(256) bf16  g_x1l[(size_t)B_*N_*512];
__device__ __align__(256) bf16  g_x2h[(size_t)B_*N_*512];
__device__ __align__(256) bf16  g_x2l[(size_t)B_*N_*512];
__device__ __align__(256) float g_H1 [(size_t)B_*N_*128];
__device__ __align__(256) float g_H2 [(size_t)B_*N_*512];
__device__ __align__(256) float g_H3 [(size_t)B_*N_*1024];
__device__ __align__(256) bf16  g_Wh [1024*1536];
__device__ __align__(256) bf16  g_Wl [1024*1536];
__device__ float g_sq [B_*N_];
__device__ float g_dis[B_*N_];
__device__ float g_pool[B_*1024];
__device__ float g_f1 [B_*512];
__device__ float g_f2 [B_*128];

// ---------------- PTX helpers ----------------
__device__ __forceinline__ uint32_t smem_u32(const void* p) {
    uint32_t a;
    asm("{ .reg .u64 t; cvta.to.shared.u64 t, %1; cvt.u32.u64 %0, t; }" : "=r"(a) : "l"(p));
    return a;
}
__device__ __forceinline__ void cpa16(uint32_t s, const void* g, int sz) {
    asm volatile("cp.async.cg.shared.global [%0], [%1], 16, %2;" :: "r"(s), "l"(g), "r"(sz));
}
#define CP_COMMIT() asm volatile("cp.async.commit_group;")
#define CP_WAIT0()  asm volatile("cp.async.wait_group 0;")

__device__ __forceinline__ void ldm4(uint32_t* r, uint32_t a) {
    asm volatile("ldmatrix.sync.aligned.m8n8.x4.shared.b16 {%0,%1,%2,%3}, [%4];"
        : "=r"(r[0]), "=r"(r[1]), "=r"(r[2]), "=r"(r[3]) : "r"(a));
}
__device__ __forceinline__ void mma_bf16(float* d, const uint32_t* a, const uint32_t* b) {
    asm volatile("mma.sync.aligned.m16n8k16.row.col.f32.bf16.bf16.f32 "
        "{%0,%1,%2,%3},{%4,%5,%6,%7},{%8,%9},{%0,%1,%2,%3};"
        : "+f"(d[0]), "+f"(d[1]), "+f"(d[2]), "+f"(d[3])
        : "r"(a[0]), "r"(a[1]), "r"(a[2]), "r"(a[3]), "r"(b[0]), "r"(b[1]));
}

// smem tile: 128 rows x 32 bf16 cols, pitch 80B (64B data + 16B pad; 5r mod 8 permutation
// => conflict-free ldmatrix). K-chunk 32, double-buffered => 80KB => 2 CTAs/SM.
#define PITCH  80
#define TILEB  (128 * PITCH)     /* 10240 bytes per operand-limb tile */
#define STAGE  (4 * TILEB)       /* Ah | Al | Bh | Bl = 40960 */
#define SMEMSZ (2 * STAGE)       /* double buffered = 81920 */

// ---------------- split-bf16 HMMA GEMM ----------------
// C[M,Nv] = sum_seg A_seg[M,Kseg] * B[Nv,K]^T  (A row-major, B K-major [Nv,K])
// MODE 0: plain   MODE 1: __expf(2v - sq_i - sq_j)   MODE 2: 2v - aux   MODE 3: relu(v + bias)
// Writes fp32 to Cf (if non-null) and split bf16 to Ch/Cl (if non-null).
template<int MODE>
__global__ __launch_bounds__(256, 2) void gemm_mma(
    const bf16* A0h, const bf16* A0l, const bf16* A1h, const bf16* A1l,
    const bf16* A2h, const bf16* A2l,
    const bf16* Bh, const bf16* Bl,
    float* Cf, bf16* Ch, bf16* Cl,
    int M, int Nv, int K, int Kseg,
    long long sA, long long sB, long long sC,
    const float* sqv, const float* aux, const float* bias)
{
    extern __shared__ char sm[];
    uint32_t sb = smem_u32(sm);
    int tid = threadIdx.x, lane = tid & 31, w = tid >> 5;
    int wm = w & 1, wn = w >> 1;          // 2 x 4 warp grid, warp tile 64x32
    int b = blockIdx.z;
    int iBase = blockIdx.y * 128, jBase = blockIdx.x * 128;

    const bf16* a0h = A0h + (size_t)b * sA;
    const bf16* a0l = A0l + (size_t)b * sA;
    const bf16* a1h = A1h + (size_t)b * sA;
    const bf16* a1l = A1l + (size_t)b * sA;
    const bf16* a2h = A2h + (size_t)b * sA;
    const bf16* a2l = A2l + (size_t)b * sA;
    const bf16* bhp = Bh + (size_t)b * sB;
    const bf16* blp = Bl + (size_t)b * sB;

    float acc[4][4][4];
    #pragma unroll
    for (int i = 0; i < 4; i++)
        #pragma unroll
        for (int j = 0; j < 4; j++)
            #pragma unroll
            for (int k = 0; k < 4; k++) acc[i][j][k] = 0.f;

    int nk = (K + 31) >> 5;
    bool vec = ((K & 31) == 0) && ((Kseg & 31) == 0);
    int Kseg2 = 2 * Kseg;

    // ---- hoisted per-thread load invariants (32-bit; all offsets < 2^31) ----
    int rA  = tid >> 2, ccA = (tid & 3) * 8;       // A: first 512-chunk group
    int rB  = (tid + 256) >> 2;                    //    second group is B rows 64..127? no:
    // chunk layout (as round 7): jj=0 -> c=tid (rows 0..63 of pair grid? no, rows 0..63?)
    // c in [0,512): r=c>>2 covers rows 0..127 over both jj groups.
    // jj=0: c=tid (0..255) -> rows 0..63 ; jj=1: c=tid+256 -> rows 64..127
    int ccB = ccA;                                 // same cc for both groups
    int rowA0 = iBase + rA;                        // A row for group 0
    int rowA1 = iBase + rA + 64;                   // A row for group 1
    int aRow0 = rowA0 * Kseg;                      // element offsets
    int aRow1 = rowA1 * Kseg;
    int gn0 = jBase + rA,   gn1 = jBase + rA + 64;
    int ok0 = (gn0 < Nv) ? 16 : 0, ok1 = (gn1 < Nv) ? 16 : 0;
    int bRow0 = (ok0 ? gn0 : 0) * K;
    int bRow1 = (ok1 ? gn1 : 0) * K;
    uint32_t so0 = (uint32_t)(rA * PITCH + (tid & 3) * 16);
    uint32_t so1 = so0 + (uint32_t)(64 * PITCH);

    auto load_vec = [&](int stg, int kc0) {
        uint32_t base = sb + stg * STAGE;
        int kg = kc0 + ccA;
        int seg = (kg >= Kseg) + (kg >= Kseg2);    // no IDIV
        const bf16* ph = (seg == 0) ? a0h : ((seg == 1) ? a1h : a2h);
        const bf16* pl = (seg == 0) ? a0l : ((seg == 1) ? a1l : a2l);
        int kloc = kg - seg * Kseg;
        // group 0 (rows 0..63)
        cpa16(base + so0,             ph + (aRow0 + kloc), 16);
        cpa16(base + so0 + TILEB,     pl + (aRow0 + kloc), 16);
        cpa16(base + so0 + 2 * TILEB, bhp + (bRow0 + kg), ok0);
        cpa16(base + so0 + 3 * TILEB, blp + (bRow0 + kg), ok0);
        // group 1 (rows 64..127)
        cpa16(base + so1,             ph + (aRow1 + kloc), 16);
        cpa16(base + so1 + TILEB,     pl + (aRow1 + kloc), 16);
        cpa16(base + so1 + 2 * TILEB, bhp + (bRow1 + kg), ok1);
        cpa16(base + so1 + 3 * TILEB, blp + (bRow1 + kg), ok1);
    };

    auto compute = [&](int stg) {
        uint32_t base = sb + stg * STAGE;
        #pragma unroll
        for (int ks = 0; ks < 2; ks++) {
            int kk = ks * 16;
            uint32_t ah[4][4], al[4][4];
            #pragma unroll
            for (int i = 0; i < 4; i++) {
                int row = wm * 64 + i * 16 + (lane & 15);
                uint32_t ca = base + (uint32_t)(row * PITCH + ((lane >> 4) * 8 + kk) * 2);
                ldm4(ah[i], ca);
                ldm4(al[i], ca + TILEB);
            }
            uint32_t bh[4][2], bl[4][2];
            #pragma unroll
            for (int jj = 0; jj < 2; jj++) {
                int rn = wn * 32 + jj * 16 + (lane & 7) + ((lane >> 4) & 1) * 8;
                uint32_t cb = base + 2 * TILEB +
                              (uint32_t)(rn * PITCH + (kk + ((lane >> 3) & 1) * 8) * 2);
                uint32_t t4[4];
                ldm4(t4, cb);
                bh[jj*2][0] = t4[0]; bh[jj*2][1] = t4[1];
                bh[jj*2+1][0] = t4[2]; bh[jj*2+1][1] = t4[3];
                ldm4(t4, cb + TILEB);
                bl[jj*2][0] = t4[0]; bl[jj*2][1] = t4[1];
                bl[jj*2+1][0] = t4[2]; bl[jj*2+1][1] = t4[3];
            }
            #pragma unroll
            for (int i = 0; i < 4; i++)
                #pragma unroll
                for (int j = 0; j < 4; j++) {
                    mma_bf16(acc[i][j], ah[i], bh[j]);   // hi*hi
                    mma_bf16(acc[i][j], ah[i], bl[j]);   // hi*lo
                    mma_bf16(acc[i][j], al[i], bh[j]);   // lo*hi
                }
        }
    };

    if (vec) {
        load_vec(0, 0); CP_COMMIT();
        for (int i = 0; i < nk; i++) {
            CP_WAIT0();
            __syncthreads();              // stage i data visible; all warps done with stage (i+1)&1
            if (i + 1 < nk) { load_vec((i + 1) & 1, (i + 1) * 32); CP_COMMIT(); }
            compute(i & 1);
        }
    } else {
        // tiny-K path (layer 1 only: K=6 or K=18)
        for (int c = tid; c < STAGE / 16; c += 256) *(uint4*)(sm + (size_t)c * 16) = make_uint4(0,0,0,0);
        __syncthreads();
        for (int i = 0; i < nk; i++) {
            for (int idx = tid; idx < 128 * 32; idx += 256) {
                int r = idx >> 5, kc = idx & 31;
                int kg = i * 32 + kc;
                uint32_t so = (uint32_t)(r * PITCH + kc * 2);
                if (kg < K) {
                    int seg = (kg >= Kseg) + (kg >= Kseg2);
                    int kkk = kg - seg * Kseg;
                    const bf16* ph = (seg == 0) ? a0h : ((seg == 1) ? a1h : a2h);
                    const bf16* pl = (seg == 0) ? a0l : ((seg == 1) ? a1l : a2l);
                    *(bf16*)(sm + so)          = ph[(size_t)(iBase + r) * Kseg + kkk];
                    *(bf16*)(sm + so + TILEB)  = pl[(size_t)(iBase + r) * Kseg + kkk];
                    int gn = jBase + r;
                    if (gn < Nv) {
                        *(bf16*)(sm + so + 2 * TILEB) = bhp[(size_t)gn * K + kg];
                        *(bf16*)(sm + so + 3 * TILEB) = blp[(size_t)gn * K + kg];
                    }
                }
            }
            __syncthreads();
            compute(0);
            __syncthreads();
            if (i + 1 < nk) {
                for (int c = tid; c < STAGE / 16; c += 256) *(uint4*)(sm + (size_t)c * 16) = make_uint4(0,0,0,0);
                __syncthreads();
            }
        }
    }

    // ---- epilogue (fused: fp32 and/or split-bf16 outputs) ----
    int g = lane >> 2, t = lane & 3;
    float* Cb  = Cf ? Cf + (size_t)b * sC : nullptr;
    bf16* Chb  = Ch ? Ch + (size_t)b * sC : nullptr;
    bf16* Clb  = Cl ? Cl + (size_t)b * sC : nullptr;
    #pragma unroll
    for (int i = 0; i < 4; i++) {
        #pragma unroll
        for (int rr = 0; rr < 2; rr++) {
            int row = iBase + wm * 64 + i * 16 + g + rr * 8;   // M is multiple of 128
            float sqi = (MODE == 1) ? sqv[b * N_ + row] : 0.f;
            #pragma unroll
            for (int j = 0; j < 4; j++) {
                int col = jBase + wn * 32 + j * 8 + 2 * t;
                #pragma unroll
                for (int cc = 0; cc < 2; cc++) {
                    int c2 = col + cc;
                    if (c2 < Nv) {
                        float v = acc[i][j][rr * 2 + cc];
                        if (MODE == 1)      v = __expf(2.f * v - sqi - sqv[b * N_ + c2]);
                        else if (MODE == 2) v = 2.f * v - aux[(size_t)b * sC + (size_t)row * Nv + c2];
                        else if (MODE == 3) v = fmaxf(v + bias[c2], 0.f);
                        size_t o = (size_t)row * Nv + c2;
                        if (Cb) Cb[o] = v;
                        if (Chb) {
                            bf16 h = __float2bfloat16(v);
                            Chb[o] = h;
                            Clb[o] = __float2bfloat16(v - __bfloat162float(h));
                        }
                    }
                }
            }
        }
    }
}

// ---------------- conversion / elementwise kernels ----------------
__global__ void split_fp32(const float* __restrict__ X, bf16* __restrict__ H, bf16* __restrict__ L, size_t n) {
    size_t i = ((size_t)blockIdx.x * 256 + threadIdx.x) * 4;
    if (i >= n) return;
    float4 v = *(const float4*)(X + i);
    bf16 hv[4], lv[4];
    float vv[4] = {v.x, v.y, v.z, v.w};
    #pragma unroll
    for (int k = 0; k < 4; k++) {
        bf16 h = __float2bfloat16(vv[k]);
        hv[k] = h;
        lv[k] = __float2bfloat16(vv[k] - __bfloat162float(h));
    }
    *(uint2*)(H + i) = *(uint2*)hv;
    *(uint2*)(L + i) = *(uint2*)lv;
}

__global__ void transpose_split(const float* __restrict__ X, bf16* __restrict__ Th, bf16* __restrict__ Tl, int F) {
    __shared__ float tile[32][33];
    int b = blockIdx.z;
    int n0 = blockIdx.x * 32, f0 = blockIdx.y * 32;
    const float* Xb = X + (size_t)b * N_ * F;
    #pragma unroll
    for (int i = 0; i < 32; i += 8) {
        int nn = n0 + threadIdx.y + i, ff = f0 + threadIdx.x;
        if (ff < F) tile[threadIdx.y + i][threadIdx.x] = Xb[(size_t)nn * F + ff];
    }
    __syncthreads();
    bf16* Thb = Th + (size_t)b * F * N_;
    bf16* Tlb = Tl + (size_t)b * F * N_;
    #pragma unroll
    for (int i = 0; i < 32; i += 8) {
        int ff = f0 + threadIdx.y + i, nn = n0 + threadIdx.x;
        if (ff < F) {
            float v = tile[threadIdx.x][threadIdx.y + i];
            bf16 h = __float2bfloat16(v);
            Thb[(size_t)ff * N_ + nn] = h;
            Tlb[(size_t)ff * N_ + nn] = __float2bfloat16(v - __bfloat162float(h));
        }
    }
}

__global__ void wtrans(const float* __restrict__ W, bf16* __restrict__ Th, bf16* __restrict__ Tl, int Fi, int Fo) {
    int kg = blockIdx.x * 32 + threadIdx.x;
    int o  = blockIdx.y * 8 + threadIdx.y;
    int Kt = 3 * Fi;
    if (kg < Kt && o < Fo) {
        int seg = (kg >= Fi) + (kg >= 2 * Fi);
        int kc = kg - seg * Fi;
        float v = W[((size_t)seg * Fi + kc) * Fo + o];
        bf16 h = __float2bfloat16(v);
        Th[(size_t)o * Kt + kg] = h;
        Tl[(size_t)o * Kt + kg] = __float2bfloat16(v - __bfloat162float(h));
    }
}

__global__ void sqnorm(const float* __restrict__ X, float* __restrict__ sq, int F) {
    int row = blockIdx.x * 8 + threadIdx.y;
    const float* r = X + (size_t)row * F;
    float s = 0.f;
    for (int f = threadIdx.x; f < F; f += 32) { float v = r[f]; s += v * v; }
    #pragma unroll
    for (int o = 16; o; o >>= 1) s += __shfl_xor_sync(0xffffffffu, s, o);
    if (threadIdx.x == 0) sq[row] = s;
}

__global__ void rowdeg(const float* __restrict__ A, float* __restrict__ dis) {
    int row = blockIdx.x * 8 + threadIdx.y;
    const float* r = A + (size_t)row * N_;
    float s = 0.f;
    for (int m = threadIdx.x; m < N_; m += 32) s += r[m];
    #pragma unroll
    for (int o = 16; o; o >>= 1) s += __shfl_xor_sync(0xffffffffu, s, o);
    if (threadIdx.x == 0) dis[row] = rsqrtf(s);
}

__global__ void makeL_split(const float* __restrict__ A, const float* __restrict__ dis,
                            bf16* __restrict__ Lh, bf16* __restrict__ Ll) {
    size_t idx = ((size_t)blockIdx.x * 256 + threadIdx.x) * 4;
    int j0 = (int)(idx & (N_ - 1));
    size_t t = idx >> 10;
    int i = (int)(t & (N_ - 1));
    int b = (int)(t >> 10);
    float di = dis[b * N_ + i];
    float4 a = *(const float4*)(A + idx);
    float av[4] = {a.x, a.y, a.z, a.w};
    bf16 hv[4], lv[4];
    #pragma unroll
    for (int k = 0; k < 4; k++) {
        float v = -di * dis[b * N_ + j0 + k] * av[k];
        if (i == j0 + k) v += 1.f;
        bf16 h = __float2bfloat16(v);
        hv[k] = h;
        lv[k] = __float2bfloat16(v - __bfloat162float(h));
    }
    *(uint2*)(Lh + idx) = *(uint2*)hv;
    *(uint2*)(Ll + idx) = *(uint2*)lv;
}

__global__ void maxpool(const float* __restrict__ H, float* __restrict__ out) {
    int f = blockIdx.x * 256 + threadIdx.x;
    int b = blockIdx.y;
    const float* base = H + (size_t)b * N_ * 1024 + f;
    float m = -1e30f;
    for (int n = 0; n < N_; n++) m = fmaxf(m, base[(size_t)n * 1024]);
    out[b * 1024 + f] = m;
}

__global__ void fckernel(const float* __restrict__ in, const float* __restrict__ W,
                         const float* __restrict__ bias, float* __restrict__ out,
                         int K, int Nout, int dorelu) {
    __shared__ float s[1024];
    int b = blockIdx.x;
    for (int i = threadIdx.x; i < K; i += blockDim.x) s[i] = in[(size_t)b * K + i];
    __syncthreads();
    for (int j = threadIdx.x; j < Nout; j += blockDim.x) {
        float acc = bias[j];
        for (int i = 0; i < K; i++) acc = fmaf(s[i], W[(size_t)i * Nout + j], acc);
        if (dorelu) acc = fmaxf(acc, 0.f);
        out[(size_t)b * Nout + j] = acc;
    }
}

// ---------------- host orchestration ----------------
struct Ptrs {
    float *A, *x1, *sq, *dis;
    bf16 *Th, *Tl, *Lh, *Ll, *x1h, *x1l, *x2h, *x2l, *Wh, *Wl;
};

// inH/inL: split of layer input P (already populated). outH/outL: split of H for next layer (may be null).
static void conv_layer(const float* P, bf16* inH, bf16* inL, int Fi, int Fo,
                       const float* W, const float* bias,
                       float* H, bf16* outH, bf16* outL, const Ptrs& p)
{
    dim3 tb32(32, 8);

    transpose_split<<<dim3(32, (Fi + 31) / 32, B_), tb32>>>(P, p.Th, p.Tl, Fi);
    sqnorm<<<B_ * N_ / 8, tb32>>>(P, p.sq, Fi);

    // adjacency: A = exp(2*X*X^T - sq_i - sq_j)
    gemm_mma<1><<<dim3(8, 8, B_), 256, SMEMSZ>>>(
        inH, inL, inH, inL, inH, inL, inH, inL,
        p.A, nullptr, nullptr,
        N_, N_, Fi, Fi, (long long)N_ * Fi, (long long)N_ * Fi, (long long)N_ * N_,
        p.sq, nullptr, nullptr);

    rowdeg<<<B_ * N_ / 8, tb32>>>(p.A, p.dis);
    makeL_split<<<(unsigned)((size_t)B_ * N_ * N_ / 1024), 256>>>(p.A, p.dis, p.Lh, p.Ll);

    // x1 = L @ x0 : fp32 (for transpose) + split bf16 (for feature gemm)
    gemm_mma<0><<<dim3((Fi + 127) / 128, 8, B_), 256, SMEMSZ>>>(
        p.Lh, p.Ll, p.Lh, p.Ll, p.Lh, p.Ll, p.Th, p.Tl,
        p.x1, p.x1h, p.x1l,
        N_, Fi, N_, N_, (long long)N_ * N_, (long long)Fi * N_, (long long)N_ * Fi,
        nullptr, nullptr, nullptr);

    transpose_split<<<dim3(32, (Fi + 31) / 32, B_), tb32>>>(p.x1, p.Th, p.Tl, Fi);

    // x2 = 2 L @ x1 - x0 : split bf16 only (no fp32 materialization)
    gemm_mma<2><<<dim3((Fi + 127) / 128, 8, B_), 256, SMEMSZ>>>(
        p.Lh, p.Ll, p.Lh, p.Ll, p.Lh, p.Ll, p.Th, p.Tl,
        nullptr, p.x2h, p.x2l,
        N_, Fi, N_, N_, (long long)N_ * N_, (long long)Fi * N_, (long long)N_ * Fi,
        nullptr, P, nullptr);

    wtrans<<<dim3((3 * Fi + 31) / 32, (Fo + 7) / 8), tb32>>>(W, p.Wh, p.Wl, Fi, Fo);

    // H = relu(x0 W0 + x1 W1 + x2 W2 + b); also emit next layer's split
    gemm_mma<3><<<dim3((Fo + 127) / 128, B_ * N_ / 128, 1), 256, SMEMSZ>>>(
        inH, inL, p.x1h, p.x1l, p.x2h, p.x2l, p.Wh, p.Wl,
        H, outH, outL,
        B_ * N_, Fo, 3 * Fi, Fi, 0, 0, 0,
        nullptr, nullptr, bias);
}

extern "C" void kernel_launch(void* const* d_in, const int* in_sizes, int n_in,
                              void* d_out, int out_size) {
    (void)in_sizes; (void)n_in; (void)out_size;
    const float* x     = (const float*)d_in[0];
    const float* W1    = (const float*)d_in[1];
    const float* b1    = (const float*)d_in[2];
    const float* W2    = (const float*)d_in[3];
    const float* b2    = (const float*)d_in[4];
    const float* W3    = (const float*)d_in[5];
    const float* b3    = (const float*)d_in[6];
    const float* fc1_w = (const float*)d_in[7];
    const float* fc1_b = (const float*)d_in[8];
    const float* fc2_w = (const float*)d_in[9];
    const float* fc2_b = (const float*)d_in[10];
    const float* fc3_w = (const float*)d_in[11];
    const float* fc3_b = (const float*)d_in[12];
    float* out = (float*)d_out;

    cudaFuncSetAttribute(gemm_mma<0>, cudaFuncAttributeMaxDynamicSharedMemorySize, SMEMSZ);
    cudaFuncSetAttribute(gemm_mma<1>, cudaFuncAttributeMaxDynamicSharedMemorySize, SMEMSZ);
    cudaFuncSetAttribute(gemm_mma<2>, cudaFuncAttributeMaxDynamicSharedMemorySize, SMEMSZ);
    cudaFuncSetAttribute(gemm_mma<3>, cudaFuncAttributeMaxDynamicSharedMemorySize, SMEMSZ);

    Ptrs p;
    bf16 *Xh, *Xl, *Yh, *Yl;
    float *H1, *H2, *H3, *pool, *f1, *f2;
    cudaGetSymbolAddress((void**)&p.A,   g_A);
    cudaGetSymbolAddress((void**)&p.x1,  g_x1);
    cudaGetSymbolAddress((void**)&p.sq,  g_sq);
    cudaGetSymbolAddress((void**)&p.dis, g_dis);
    cudaGetSymbolAddress((void**)&Xh,    g_Xh);
    cudaGetSymbolAddress((void**)&Xl,    g_Xl);
    cudaGetSymbolAddress((void**)&Yh,    g_Yh);
    cudaGetSymbolAddress((void**)&Yl,    g_Yl);
    cudaGetSymbolAddress((void**)&p.Th,  g_Th);
    cudaGetSymbolAddress((void**)&p.Tl,  g_Tl);
    cudaGetSymbolAddress((void**)&p.Lh,  g_Lh);
    cudaGetSymbolAddress((void**)&p.Ll,  g_Ll);
    cudaGetSymbolAddress((void**)&p.x1h, g_x1h);
    cudaGetSymbolAddress((void**)&p.x1l, g_x1l);
    cudaGetSymbolAddress((void**)&p.x2h, g_x2h);
    cudaGetSymbolAddress((void**)&p.x2l, g_x2l);
    cudaGetSymbolAddress((void**)&p.Wh,  g_Wh);
    cudaGetSymbolAddress((void**)&p.Wl,  g_Wl);
    cudaGetSymbolAddress((void**)&H1,    g_H1);
    cudaGetSymbolAddress((void**)&H2,    g_H2);
    cudaGetSymbolAddress((void**)&H3,    g_H3);
    cudaGetSymbolAddress((void**)&pool,  g_pool);
    cudaGetSymbolAddress((void**)&f1,    g_f1);
    cudaGetSymbolAddress((void**)&f2,    g_f2);

    // layer 1: split the raw input, H1 split -> Y
    split_fp32<<<(unsigned)(((size_t)B_ * N_ * 6 + 1023) / 1024), 256>>>(x, Xh, Xl, (size_t)B_ * N_ * 6);
    conv_layer(x,  Xh, Xl, 6,   128,  W1, b1, H1, Yh, Yl, p);
    // layer 2: input split = Y, H2 split -> X (ping-pong)
    conv_layer(H1, Yh, Yl, 128, 512,  W2, b2, H2, Xh, Xl, p);
    // layer 3: input split = X, no H split needed
    conv_layer(H2, Xh, Xl, 512, 1024, W3, b3, H3, nullptr, nullptr, p);

    maxpool<<<dim3(4, B_), 256>>>(H3, pool);
    fckernel<<<B_, 256>>>(pool, fc1_w, fc1_b, f1, 1024, 512, 1);
    fckernel<<<B_, 256>>>(f1,   fc2_w, fc2_b, f2, 512, 128, 1);
    fckernel<<<B_, 256>>>(f2,   fc3_w, fc3_b, out, 128, 40, 0);
}

// round 12
// speedup vs baseline: 1.4733x; 1.4733x over previous
#include <cuda_runtime.h>
#include <cuda_bf16.h>
#include <math.h>
#include <stdint.h>

#define B_ 32
#define N_ 1024
typedef __nv_bfloat16 bf16;

// ---------------- scratch (static device memory; no runtime alloc) ----------------
__device__ __align__(256) float g_A  [(size_t)B_*N_*N_];     // adjacency fp32
__device__ __align__(256) bf16  g_Lh [(size_t)B_*N_*N_];     // Laplacian hi
__device__ __align__(256) bf16  g_Ll [(size_t)B_*N_*N_];     // Laplacian lo
__device__ __align__(256) bf16  g_Xh [(size_t)B_*N_*512];    // layer input split (ping)
__device__ __align__(256) bf16  g_Xl [(size_t)B_*N_*512];
__device__ __align__(256) bf16  g_Yh [(size_t)B_*N_*512];    // layer input split (pong)
__device__ __align__(256) bf16  g_Yl [(size_t)B_*N_*512];
__device__ __align__(256) bf16  g_Th [(size_t)B_*512*N_];    // transposed operand split
__device__ __align__(256) bf16  g_Tl [(size_t)B_*512*N_];
__device__ __align__(256) float g_x1 [(size_t)B_*N_*512];
__device__ __align__(256) bf16  g_x1h[(size_t)B_*N_*512];
__device__ __align__(256) bf16  g_x1l[(size_t)B_*N_*512];
__device__ __align__(256) bf16  g_x2h[(size_t)B_*N_*512];
__device__ __align__(256) bf16  g_x2l[(size_t)B_*N_*512];
__device__ __align__(256) float g_H1 [(size_t)B_*N_*128];
__device__ __align__(256) float g_H2 [(size_t)B_*N_*512];
__device__ __align__(256) float g_H3 [(size_t)B_*N_*1024];
__device__ __align__(256) bf16  g_Wh [1024*1536];
__device__ __align__(256) bf16  g_Wl [1024*1536];
__device__ float g_sq [B_*N_];
__device__ float g_dis[B_*N_];
__device__ float g_pool[B_*1024];
__device__ float g_f1 [B_*512];
__device__ float g_f2 [B_*128];

// ---------------- PTX helpers ----------------
__device__ __forceinline__ uint32_t smem_u32(const void* p) {
    uint32_t a;
    asm("{ .reg .u64 t; cvta.to.shared.u64 t, %1; cvt.u32.u64 %0, t; }" : "=r"(a) : "l"(p));
    return a;
}
__device__ __forceinline__ void cpa16(uint32_t s, const void* g, int sz) {
    asm volatile("cp.async.cg.shared.global [%0], [%1], 16, %2;" :: "r"(s), "l"(g), "r"(sz));
}
#define CP_COMMIT() asm volatile("cp.async.commit_group;")
#define CP_WAIT0()  asm volatile("cp.async.wait_group 0;")
#define CP_WAIT1()  asm volatile("cp.async.wait_group 1;")

__device__ __forceinline__ void ldm4(uint32_t* r, uint32_t a) {
    asm volatile("ldmatrix.sync.aligned.m8n8.x4.shared.b16 {%0,%1,%2,%3}, [%4];"
        : "=r"(r[0]), "=r"(r[1]), "=r"(r[2]), "=r"(r[3]) : "r"(a));
}
__device__ __forceinline__ void mma_bf16(float* d, const uint32_t* a, const uint32_t* b) {
    asm volatile("mma.sync.aligned.m16n8k16.row.col.f32.bf16.bf16.f32 "
        "{%0,%1,%2,%3},{%4,%5,%6,%7},{%8,%9},{%0,%1,%2,%3};"
        : "+f"(d[0]), "+f"(d[1]), "+f"(d[2]), "+f"(d[3])
        : "r"(a[0]), "r"(a[1]), "r"(a[2]), "r"(a[3]), "r"(b[0]), "r"(b[1]));
}

// smem tile: 128 rows x 32 bf16 cols, pitch 80B (64B data + 16B pad; 5r mod 8 permutation
// => conflict-free ldmatrix). K-chunk 32, double-buffered => 80KB => 2 CTAs/SM.
#define PITCH  80
#define TILEB  (128 * PITCH)     /* 10240 bytes per operand-limb tile */
#define STAGE  (4 * TILEB)       /* Ah | Al | Bh | Bl = 40960 */
#define SMEMSZ (2 * STAGE)       /* double buffered = 81920 */

// ---------------- split-bf16 HMMA GEMM ----------------
// C[M,Nv] = sum_seg A_seg[M,Kseg] * B[Nv,K]^T  (A row-major, B K-major [Nv,K])
// MODE 0: plain   MODE 1: __expf(2v - sq_i - sq_j)   MODE 2: 2v - aux   MODE 3: relu(v + bias)
// Writes fp32 to Cf (if non-null) and split bf16 to Ch/Cl (if non-null).
template<int MODE>
__global__ __launch_bounds__(256, 2) void gemm_mma(
    const bf16* A0h, const bf16* A0l, const bf16* A1h, const bf16* A1l,
    const bf16* A2h, const bf16* A2l,
    const bf16* Bh, const bf16* Bl,
    float* Cf, bf16* Ch, bf16* Cl,
    int M, int Nv, int K, int Kseg,
    long long sA, long long sB, long long sC,
    const float* sqv, const float* aux, const float* bias)
{
    extern __shared__ char sm[];
    uint32_t sb = smem_u32(sm);
    int tid = threadIdx.x, lane = tid & 31, w = tid >> 5;
    int wm = w & 1, wn = w >> 1;          // 2 x 4 warp grid, warp tile 64x32
    int b = blockIdx.z;
    int iBase = blockIdx.y * 128, jBase = blockIdx.x * 128;

    const bf16* a0h = A0h + (size_t)b * sA;
    const bf16* a0l = A0l + (size_t)b * sA;
    const bf16* a1h = A1h + (size_t)b * sA;
    const bf16* a1l = A1l + (size_t)b * sA;
    const bf16* a2h = A2h + (size_t)b * sA;
    const bf16* a2l = A2l + (size_t)b * sA;
    const bf16* bhp = Bh + (size_t)b * sB;
    const bf16* blp = Bl + (size_t)b * sB;

    float acc[4][4][4];
    #pragma unroll
    for (int i = 0; i < 4; i++)
        #pragma unroll
        for (int j = 0; j < 4; j++)
            #pragma unroll
            for (int k = 0; k < 4; k++) acc[i][j][k] = 0.f;

    int nk = (K + 31) >> 5;
    bool vec = ((K & 31) == 0) && ((Kseg & 31) == 0);
    int Kseg2 = 2 * Kseg;

    // ---- hoisted per-thread load invariants (32-bit; all offsets < 2^31) ----
    // chunk layout (identical to round 7): jj=0 -> rows 0..63, jj=1 -> rows 64..127
    int rA  = tid >> 2;                       // row within group
    int ccA = (tid & 3) * 8;                  // k-element offset of this 16B chunk
    int aRow0 = (iBase + rA) * Kseg;
    int aRow1 = (iBase + rA + 64) * Kseg;
    int gn0 = jBase + rA, gn1 = jBase + rA + 64;
    int ok0 = (gn0 < Nv) ? 16 : 0, ok1 = (gn1 < Nv) ? 16 : 0;
    int bRow0 = (ok0 ? gn0 : 0) * K;
    int bRow1 = (ok1 ? gn1 : 0) * K;
    uint32_t so0 = (uint32_t)(rA * PITCH + (tid & 3) * 16);
    uint32_t so1 = so0 + (uint32_t)(64 * PITCH);

    auto load_vec = [&](int stg, int kc0) {
        uint32_t base = sb + stg * STAGE;
        int kg = kc0 + ccA;
        int seg = (kg >= Kseg) + (kg >= Kseg2);       // comparison-based, no IDIV
        const bf16* ph = (seg == 0) ? a0h : ((seg == 1) ? a1h : a2h);
        const bf16* pl = (seg == 0) ? a0l : ((seg == 1) ? a1l : a2l);
        int kloc = kg - seg * Kseg;
        // group 0 (rows 0..63)
        cpa16(base + so0,             ph + (aRow0 + kloc), 16);
        cpa16(base + so0 + TILEB,     pl + (aRow0 + kloc), 16);
        cpa16(base + so0 + 2 * TILEB, bhp + (bRow0 + kg), ok0);
        cpa16(base + so0 + 3 * TILEB, blp + (bRow0 + kg), ok0);
        // group 1 (rows 64..127)
        cpa16(base + so1,             ph + (aRow1 + kloc), 16);
        cpa16(base + so1 + TILEB,     pl + (aRow1 + kloc), 16);
        cpa16(base + so1 + 2 * TILEB, bhp + (bRow1 + kg), ok1);
        cpa16(base + so1 + 3 * TILEB, blp + (bRow1 + kg), ok1);
    };

    auto compute = [&](int stg) {
        uint32_t base = sb + stg * STAGE;
        #pragma unroll
        for (int ks = 0; ks < 2; ks++) {
            int kk = ks * 16;
            uint32_t ah[4][4], al[4][4];
            #pragma unroll
            for (int i = 0; i < 4; i++) {
                int row = wm * 64 + i * 16 + (lane & 15);
                uint32_t ca = base + (uint32_t)(row * PITCH + ((lane >> 4) * 8 + kk) * 2);
                ldm4(ah[i], ca);
                ldm4(al[i], ca + TILEB);
            }
            uint32_t bh[4][2], bl[4][2];
            #pragma unroll
            for (int jj = 0; jj < 2; jj++) {
                int rn = wn * 32 + jj * 16 + (lane & 7) + ((lane >> 4) & 1) * 8;
                uint32_t cb = base + 2 * TILEB +
                              (uint32_t)(rn * PITCH + (kk + ((lane >> 3) & 1) * 8) * 2);
                uint32_t t4[4];
                ldm4(t4, cb);
                bh[jj*2][0] = t4[0]; bh[jj*2][1] = t4[1];
                bh[jj*2+1][0] = t4[2]; bh[jj*2+1][1] = t4[3];
                ldm4(t4, cb + TILEB);
                bl[jj*2][0] = t4[0]; bl[jj*2][1] = t4[1];
                bl[jj*2+1][0] = t4[2]; bl[jj*2+1][1] = t4[3];
            }
            #pragma unroll
            for (int i = 0; i < 4; i++)
                #pragma unroll
                for (int j = 0; j < 4; j++) {
                    mma_bf16(acc[i][j], ah[i], bh[j]);   // hi*hi
                    mma_bf16(acc[i][j], ah[i], bl[j]);   // hi*lo
                    mma_bf16(acc[i][j], al[i], bh[j]);   // lo*hi
                }
        }
    };

    if (vec) {
        // round-7 proven pipeline: load(i+1); commit; wait1; sync; compute(i); sync
        load_vec(0, 0); CP_COMMIT();
        for (int i = 0; i < nk; i++) {
            if (i + 1 < nk) { load_vec((i + 1) & 1, (i + 1) * 32); CP_COMMIT(); CP_WAIT1(); }
            else            { CP_WAIT0(); }
            __syncthreads();
            compute(i & 1);
            __syncthreads();
        }
    } else {
        // tiny-K path (layer 1 only: K=6 or K=18)
        for (int c = tid; c < STAGE / 16; c += 256) *(uint4*)(sm + (size_t)c * 16) = make_uint4(0,0,0,0);
        __syncthreads();
        for (int i = 0; i < nk; i++) {
            for (int idx = tid; idx < 128 * 32; idx += 256) {
                int r = idx >> 5, kc = idx & 31;
                int kg = i * 32 + kc;
                uint32_t so = (uint32_t)(r * PITCH + kc * 2);
                if (kg < K) {
                    int seg = (kg >= Kseg) + (kg >= Kseg2);
                    int kkk = kg - seg * Kseg;
                    const bf16* ph = (seg == 0) ? a0h : ((seg == 1) ? a1h : a2h);
                    const bf16* pl = (seg == 0) ? a0l : ((seg == 1) ? a1l : a2l);
                    *(bf16*)(sm + so)          = ph[(size_t)(iBase + r) * Kseg + kkk];
                    *(bf16*)(sm + so + TILEB)  = pl[(size_t)(iBase + r) * Kseg + kkk];
                    int gn = jBase + r;
                    if (gn < Nv) {
                        *(bf16*)(sm + so + 2 * TILEB) = bhp[(size_t)gn * K + kg];
                        *(bf16*)(sm + so + 3 * TILEB) = blp[(size_t)gn * K + kg];
                    }
                }
            }
            __syncthreads();
            compute(0);
            __syncthreads();
            if (i + 1 < nk) {
                for (int c = tid; c < STAGE / 16; c += 256) *(uint4*)(sm + (size_t)c * 16) = make_uint4(0,0,0,0);
                __syncthreads();
            }
        }
    }

    // ---- epilogue (fused: fp32 and/or split-bf16 outputs) ----
    int g = lane >> 2, t = lane & 3;
    float* Cb  = Cf ? Cf + (size_t)b * sC : nullptr;
    bf16* Chb  = Ch ? Ch + (size_t)b * sC : nullptr;
    bf16* Clb  = Cl ? Cl + (size_t)b * sC : nullptr;
    #pragma unroll
    for (int i = 0; i < 4; i++) {
        #pragma unroll
        for (int rr = 0; rr < 2; rr++) {
            int row = iBase + wm * 64 + i * 16 + g + rr * 8;   // M is multiple of 128
            float sqi = (MODE == 1) ? sqv[b * N_ + row] : 0.f;
            #pragma unroll
            for (int j = 0; j < 4; j++) {
                int col = jBase + wn * 32 + j * 8 + 2 * t;
                #pragma unroll
                for (int cc = 0; cc < 2; cc++) {
                    int c2 = col + cc;
                    if (c2 < Nv) {
                        float v = acc[i][j][rr * 2 + cc];
                        if (MODE == 1)      v = __expf(2.f * v - sqi - sqv[b * N_ + c2]);
                        else if (MODE == 2) v = 2.f * v - aux[(size_t)b * sC + (size_t)row * Nv + c2];
                        else if (MODE == 3) v = fmaxf(v + bias[c2], 0.f);
                        size_t o = (size_t)row * Nv + c2;
                        if (Cb) Cb[o] = v;
                        if (Chb) {
                            bf16 h = __float2bfloat16(v);
                            Chb[o] = h;
                            Clb[o] = __float2bfloat16(v - __bfloat162float(h));
                        }
                    }
                }
            }
        }
    }
}

// ---------------- conversion / elementwise kernels ----------------
__global__ void split_fp32(const float* __restrict__ X, bf16* __restrict__ H, bf16* __restrict__ L, size_t n) {
    size_t i = ((size_t)blockIdx.x * 256 + threadIdx.x) * 4;
    if (i >= n) return;
    float4 v = *(const float4*)(X + i);
    bf16 hv[4], lv[4];
    float vv[4] = {v.x, v.y, v.z, v.w};
    #pragma unroll
    for (int k = 0; k < 4; k++) {
        bf16 h = __float2bfloat16(vv[k]);
        hv[k] = h;
        lv[k] = __float2bfloat16(vv[k] - __bfloat162float(h));
    }
    *(uint2*)(H + i) = *(uint2*)hv;
    *(uint2*)(L + i) = *(uint2*)lv;
}

__global__ void transpose_split(const float* __restrict__ X, bf16* __restrict__ Th, bf16* __restrict__ Tl, int F) {
    __shared__ float tile[32][33];
    int b = blockIdx.z;
    int n0 = blockIdx.x * 32, f0 = blockIdx.y * 32;
    const float* Xb = X + (size_t)b * N_ * F;
    #pragma unroll
    for (int i = 0; i < 32; i += 8) {
        int nn = n0 + threadIdx.y + i, ff = f0 + threadIdx.x;
        if (ff < F) tile[threadIdx.y + i][threadIdx.x] = Xb[(size_t)nn * F + ff];
    }
    __syncthreads();
    bf16* Thb = Th + (size_t)b * F * N_;
    bf16* Tlb = Tl + (size_t)b * F * N_;
    #pragma unroll
    for (int i = 0; i < 32; i += 8) {
        int ff = f0 + threadIdx.y + i, nn = n0 + threadIdx.x;
        if (ff < F) {
            float v = tile[threadIdx.x][threadIdx.y + i];
            bf16 h = __float2bfloat16(v);
            Thb[(size_t)ff * N_ + nn] = h;
            Tlb[(size_t)ff * N_ + nn] = __float2bfloat16(v - __bfloat162float(h));
        }
    }
}

__global__ void wtrans(const float* __restrict__ W, bf16* __restrict__ Th, bf16* __restrict__ Tl, int Fi, int Fo) {
    int kg = blockIdx.x * 32 + threadIdx.x;
    int o  = blockIdx.y * 8 + threadIdx.y;
    int Kt = 3 * Fi;
    if (kg < Kt && o < Fo) {
        int seg = (kg >= Fi) + (kg >= 2 * Fi);
        int kc = kg - seg * Fi;
        float v = W[((size_t)seg * Fi + kc) * Fo + o];
        bf16 h = __float2bfloat16(v);
        Th[(size_t)o * Kt + kg] = h;
        Tl[(size_t)o * Kt + kg] = __float2bfloat16(v - __bfloat162float(h));
    }
}

__global__ void sqnorm(const float* __restrict__ X, float* __restrict__ sq, int F) {
    int row = blockIdx.x * 8 + threadIdx.y;
    const float* r = X + (size_t)row * F;
    float s = 0.f;
    for (int f = threadIdx.x; f < F; f += 32) { float v = r[f]; s += v * v; }
    #pragma unroll
    for (int o = 16; o; o >>= 1) s += __shfl_xor_sync(0xffffffffu, s, o);
    if (threadIdx.x == 0) sq[row] = s;
}

__global__ void rowdeg(const float* __restrict__ A, float* __restrict__ dis) {
    int row = blockIdx.x * 8 + threadIdx.y;
    const float* r = A + (size_t)row * N_;
    float s = 0.f;
    for (int m = threadIdx.x; m < N_; m += 32) s += r[m];
    #pragma unroll
    for (int o = 16; o; o >>= 1) s += __shfl_xor_sync(0xffffffffu, s, o);
    if (threadIdx.x == 0) dis[row] = rsqrtf(s);
}

__global__ void makeL_split(const float* __restrict__ A, const float* __restrict__ dis,
                            bf16* __restrict__ Lh, bf16* __restrict__ Ll) {
    size_t idx = ((size_t)blockIdx.x * 256 + threadIdx.x) * 4;
    int j0 = (int)(idx & (N_ - 1));
    size_t t = idx >> 10;
    int i = (int)(t & (N_ - 1));
    int b = (int)(t >> 10);
    float di = dis[b * N_ + i];
    float4 a = *(const float4*)(A + idx);
    float av[4] = {a.x, a.y, a.z, a.w};
    bf16 hv[4], lv[4];
    #pragma unroll
    for (int k = 0; k < 4; k++) {
        float v = -di * dis[b * N_ + j0 + k] * av[k];
        if (i == j0 + k) v += 1.f;
        bf16 h = __float2bfloat16(v);
        hv[k] = h;
        lv[k] = __float2bfloat16(v - __bfloat162float(h));
    }
    *(uint2*)(Lh + idx) = *(uint2*)hv;
    *(uint2*)(Ll + idx) = *(uint2*)lv;
}

__global__ void maxpool(const float* __restrict__ H, float* __restrict__ out) {
    int f = blockIdx.x * 256 + threadIdx.x;
    int b = blockIdx.y;
    const float* base = H + (size_t)b * N_ * 1024 + f;
    float m = -1e30f;
    for (int n = 0; n < N_; n++) m = fmaxf(m, base[(size_t)n * 1024]);
    out[b * 1024 + f] = m;
}

__global__ void fckernel(const float* __restrict__ in, const float* __restrict__ W,
                         const float* __restrict__ bias, float* __restrict__ out,
                         int K, int Nout, int dorelu) {
    __shared__ float s[1024];
    int b = blockIdx.x;
    for (int i = threadIdx.x; i < K; i += blockDim.x) s[i] = in[(size_t)b * K + i];
    __syncthreads();
    for (int j = threadIdx.x; j < Nout; j += blockDim.x) {
        float acc = bias[j];
        for (int i = 0; i < K; i++) acc = fmaf(s[i], W[(size_t)i * Nout + j], acc);
        if (dorelu) acc = fmaxf(acc, 0.f);
        out[(size_t)b * Nout + j] = acc;
    }
}

// ---------------- host orchestration ----------------
struct Ptrs {
    float *A, *x1, *sq, *dis;
    bf16 *Th, *Tl, *Lh, *Ll, *x1h, *x1l, *x2h, *x2l, *Wh, *Wl;
};

// inH/inL: split of layer input P (already populated). outH/outL: split of H for next layer (may be null).
static void conv_layer(const float* P, bf16* inH, bf16* inL, int Fi, int Fo,
                       const float* W, const float* bias,
                       float* H, bf16* outH, bf16* outL, const Ptrs& p)
{
    dim3 tb32(32, 8);

    transpose_split<<<dim3(32, (Fi + 31) / 32, B_), tb32>>>(P, p.Th, p.Tl, Fi);
    sqnorm<<<B_ * N_ / 8, tb32>>>(P, p.sq, Fi);

    // adjacency: A = exp(2*X*X^T - sq_i - sq_j)
    gemm_mma<1><<<dim3(8, 8, B_), 256, SMEMSZ>>>(
        inH, inL, inH, inL, inH, inL, inH, inL,
        p.A, nullptr, nullptr,
        N_, N_, Fi, Fi, (long long)N_ * Fi, (long long)N_ * Fi, (long long)N_ * N_,
        p.sq, nullptr, nullptr);

    rowdeg<<<B_ * N_ / 8, tb32>>>(p.A, p.dis);
    makeL_split<<<(unsigned)((size_t)B_ * N_ * N_ / 1024), 256>>>(p.A, p.dis, p.Lh, p.Ll);

    // x1 = L @ x0 : fp32 (for transpose) + split bf16 (for feature gemm)
    gemm_mma<0><<<dim3((Fi + 127) / 128, 8, B_), 256, SMEMSZ>>>(
        p.Lh, p.Ll, p.Lh, p.Ll, p.Lh, p.Ll, p.Th, p.Tl,
        p.x1, p.x1h, p.x1l,
        N_, Fi, N_, N_, (long long)N_ * N_, (long long)Fi * N_, (long long)N_ * Fi,
        nullptr, nullptr, nullptr);

    transpose_split<<<dim3(32, (Fi + 31) / 32, B_), tb32>>>(p.x1, p.Th, p.Tl, Fi);

    // x2 = 2 L @ x1 - x0 : split bf16 only (no fp32 materialization)
    gemm_mma<2><<<dim3((Fi + 127) / 128, 8, B_), 256, SMEMSZ>>>(
        p.Lh, p.Ll, p.Lh, p.Ll, p.Lh, p.Ll, p.Th, p.Tl,
        nullptr, p.x2h, p.x2l,
        N_, Fi, N_, N_, (long long)N_ * N_, (long long)Fi * N_, (long long)N_ * Fi,
        nullptr, P, nullptr);

    wtrans<<<dim3((3 * Fi + 31) / 32, (Fo + 7) / 8), tb32>>>(W, p.Wh, p.Wl, Fi, Fo);

    // H = relu(x0 W0 + x1 W1 + x2 W2 + b); also emit next layer's split
    gemm_mma<3><<<dim3((Fo + 127) / 128, B_ * N_ / 128, 1), 256, SMEMSZ>>>(
        inH, inL, p.x1h, p.x1l, p.x2h, p.x2l, p.Wh, p.Wl,
        H, outH, outL,
        B_ * N_, Fo, 3 * Fi, Fi, 0, 0, 0,
        nullptr, nullptr, bias);
}

extern "C" void kernel_launch(void* const* d_in, const int* in_sizes, int n_in,
                              void* d_out, int out_size) {
    (void)in_sizes; (void)n_in; (void)out_size;
    const float* x     = (const float*)d_in[0];
    const float* W1    = (const float*)d_in[1];
    const float* b1    = (const float*)d_in[2];
    const float* W2    = (const float*)d_in[3];
    const float* b2    = (const float*)d_in[4];
    const float* W3    = (const float*)d_in[5];
    const float* b3    = (const float*)d_in[6];
    const float* fc1_w = (const float*)d_in[7];
    const float* fc1_b = (const float*)d_in[8];
    const float* fc2_w = (const float*)d_in[9];
    const float* fc2_b = (const float*)d_in[10];
    const float* fc3_w = (const float*)d_in[11];
    const float* fc3_b = (const float*)d_in[12];
    float* out = (float*)d_out;

    cudaFuncSetAttribute(gemm_mma<0>, cudaFuncAttributeMaxDynamicSharedMemorySize, SMEMSZ);
    cudaFuncSetAttribute(gemm_mma<1>, cudaFuncAttributeMaxDynamicSharedMemorySize, SMEMSZ);
    cudaFuncSetAttribute(gemm_mma<2>, cudaFuncAttributeMaxDynamicSharedMemorySize, SMEMSZ);
    cudaFuncSetAttribute(gemm_mma<3>, cudaFuncAttributeMaxDynamicSharedMemorySize, SMEMSZ);

    Ptrs p;
    bf16 *Xh, *Xl, *Yh, *Yl;
    float *H1, *H2, *H3, *pool, *f1, *f2;
    cudaGetSymbolAddress((void**)&p.A,   g_A);
    cudaGetSymbolAddress((void**)&p.x1,  g_x1);
    cudaGetSymbolAddress((void**)&p.sq,  g_sq);
    cudaGetSymbolAddress((void**)&p.dis, g_dis);
    cudaGetSymbolAddress((void**)&Xh,    g_Xh);
    cudaGetSymbolAddress((void**)&Xl,    g_Xl);
    cudaGetSymbolAddress((void**)&Yh,    g_Yh);
    cudaGetSymbolAddress((void**)&Yl,    g_Yl);
    cudaGetSymbolAddress((void**)&p.Th,  g_Th);
    cudaGetSymbolAddress((void**)&p.Tl,  g_Tl);
    cudaGetSymbolAddress((void**)&p.Lh,  g_Lh);
    cudaGetSymbolAddress((void**)&p.Ll,  g_Ll);
    cudaGetSymbolAddress((void**)&p.x1h, g_x1h);
    cudaGetSymbolAddress((void**)&p.x1l, g_x1l);
    cudaGetSymbolAddress((void**)&p.x2h, g_x2h);
    cudaGetSymbolAddress((void**)&p.x2l, g_x2l);
    cudaGetSymbolAddress((void**)&p.Wh,  g_Wh);
    cudaGetSymbolAddress((void**)&p.Wl,  g_Wl);
    cudaGetSymbolAddress((void**)&H1,    g_H1);
    cudaGetSymbolAddress((void**)&H2,    g_H2);
    cudaGetSymbolAddress((void**)&H3,    g_H3);
    cudaGetSymbolAddress((void**)&pool,  g_pool);
    cudaGetSymbolAddress((void**)&f1,    g_f1);
    cudaGetSymbolAddress((void**)&f2,    g_f2);

    // layer 1: split the raw input, H1 split -> Y
    split_fp32<<<(unsigned)(((size_t)B_ * N_ * 6 + 1023) / 1024), 256>>>(x, Xh, Xl, (size_t)B_ * N_ * 6);
    conv_layer(x,  Xh, Xl, 6,   128,  W1, b1, H1, Yh, Yl, p);
    // layer 2: input split = Y, H2 split -> X (ping-pong)
    conv_layer(H1, Yh, Yl, 128, 512,  W2, b2, H2, Xh, Xl, p);
    // layer 3: input split = X, no H split needed
    conv_layer(H2, Xh, Xl, 512, 1024, W3, b3, H3, nullptr, nullptr, p);

    maxpool<<<dim3(4, B_), 256>>>(H3, pool);
    fckernel<<<B_, 256>>>(pool, fc1_w, fc1_b, f1, 1024, 512, 1);
    fckernel<<<B_, 256>>>(f1,   fc2_w, fc2_b, f2, 512, 128, 1);
    fckernel<<<B_, 256>>>(f2,   fc3_w, fc3_b, out, 128, 40, 0);
}

// round 13
// speedup vs baseline: 1.6037x; 1.0885x over previous
#include <cuda_runtime.h>
#include <cuda_bf16.h>
#include <math.h>
#include <stdint.h>

#define B_ 32
#define N_ 1024
typedef __nv_bfloat16 bf16;

// ---------------- scratch (static device memory; no runtime alloc) ----------------
__device__ __align__(256) float g_A  [(size_t)B_*N_*N_];     // adjacency fp32
__device__ __align__(256) bf16  g_Lh [(size_t)B_*N_*N_];     // Laplacian hi
__device__ __align__(256) bf16  g_Ll [(size_t)B_*N_*N_];     // Laplacian lo
__device__ __align__(256) bf16  g_Xh [(size_t)B_*N_*512];    // layer input split (ping)
__device__ __align__(256) bf16  g_Xl [(size_t)B_*N_*512];
__device__ __align__(256) bf16  g_Yh [(size_t)B_*N_*512];    // layer input split (pong)
__device__ __align__(256) bf16  g_Yl [(size_t)B_*N_*512];
__device__ __align__(256) bf16  g_Th [(size_t)B_*512*N_];    // transposed layer-input split
__device__ __align__(256) bf16  g_Tl [(size_t)B_*512*N_];
__device__ __align__(256) bf16  g_T2h[(size_t)B_*512*N_];    // transposed x1 split (epilogue-fused)
__device__ __align__(256) bf16  g_T2l[(size_t)B_*512*N_];
__device__ __align__(256) bf16  g_x1h[(size_t)B_*N_*512];
__device__ __align__(256) bf16  g_x1l[(size_t)B_*N_*512];
__device__ __align__(256) bf16  g_x2h[(size_t)B_*N_*512];
__device__ __align__(256) bf16  g_x2l[(size_t)B_*N_*512];
__device__ __align__(256) float g_H1 [(size_t)B_*N_*128];
__device__ __align__(256) float g_H2 [(size_t)B_*N_*512];
__device__ __align__(256) float g_H3 [(size_t)B_*N_*1024];
__device__ __align__(256) bf16  g_Wh [1024*1536];
__device__ __align__(256) bf16  g_Wl [1024*1536];
__device__ float g_sq [B_*N_];
__device__ float g_dis[B_*N_];
__device__ float g_pool[B_*1024];
__device__ float g_f1 [B_*512];
__device__ float g_f2 [B_*128];

// ---------------- PTX helpers ----------------
__device__ __forceinline__ uint32_t smem_u32(const void* p) {
    uint32_t a;
    asm("{ .reg .u64 t; cvta.to.shared.u64 t, %1; cvt.u32.u64 %0, t; }" : "=r"(a) : "l"(p));
    return a;
}
__device__ __forceinline__ void cpa16(uint32_t s, const void* g, int sz) {
    asm volatile("cp.async.cg.shared.global [%0], [%1], 16, %2;" :: "r"(s), "l"(g), "r"(sz));
}
#define CP_COMMIT() asm volatile("cp.async.commit_group;")
#define CP_WAIT0()  asm volatile("cp.async.wait_group 0;")
#define CP_WAIT1()  asm volatile("cp.async.wait_group 1;")

__device__ __forceinline__ void ldm4(uint32_t* r, uint32_t a) {
    asm volatile("ldmatrix.sync.aligned.m8n8.x4.shared.b16 {%0,%1,%2,%3}, [%4];"
        : "=r"(r[0]), "=r"(r[1]), "=r"(r[2]), "=r"(r[3]) : "r"(a));
}
__device__ __forceinline__ void mma_bf16(float* d, const uint32_t* a, const uint32_t* b) {
    asm volatile("mma.sync.aligned.m16n8k16.row.col.f32.bf16.bf16.f32 "
        "{%0,%1,%2,%3},{%4,%5,%6,%7},{%8,%9},{%0,%1,%2,%3};"
        : "+f"(d[0]), "+f"(d[1]), "+f"(d[2]), "+f"(d[3])
        : "r"(a[0]), "r"(a[1]), "r"(a[2]), "r"(a[3]), "r"(b[0]), "r"(b[1]));
}

// smem tile: 128 rows x 32 bf16 cols, pitch 80B (64B data + 16B pad; 5r mod 8 permutation
// => conflict-free ldmatrix). K-chunk 32, double-buffered => 80KB => 2 CTAs/SM.
#define PITCH  80
#define TILEB  (128 * PITCH)     /* 10240 bytes per operand-limb tile */
#define STAGE  (4 * TILEB)       /* Ah | Al | Bh | Bl = 40960 */
#define SMEMSZ (2 * STAGE)       /* double buffered = 81920 */

// ---------------- split-bf16 HMMA GEMM ----------------
// C[M,Nv] = sum_seg A_seg[M,Kseg] * B[Nv,K]^T  (A row-major, B K-major [Nv,K])
// MODE 0: plain   MODE 1: __expf(2v - sq_i - sq_j), SYMMETRIC (bx<=by only, mirror write)
// MODE 2: 2v - aux   MODE 3: relu(v + bias)
// Writes fp32 to Cf, split bf16 to Ch/Cl, transposed split bf16 to Cth/Ctl (each if non-null).
template<int MODE>
__global__ __launch_bounds__(256, 2) void gemm_mma(
    const bf16* A0h, const bf16* A0l, const bf16* A1h, const bf16* A1l,
    const bf16* A2h, const bf16* A2l,
    const bf16* Bh, const bf16* Bl,
    float* Cf, bf16* Ch, bf16* Cl, bf16* Cth, bf16* Ctl,
    int M, int Nv, int K, int Kseg,
    long long sA, long long sB, long long sC, long long sT,
    const float* sqv, const float* aux, const float* bias)
{
    if (MODE == 1 && blockIdx.x > blockIdx.y) return;   // symmetric: skip upper-tri blocks

    extern __shared__ char sm[];
    uint32_t sb = smem_u32(sm);
    int tid = threadIdx.x, lane = tid & 31, w = tid >> 5;
    int wm = w & 1, wn = w >> 1;          // 2 x 4 warp grid, warp tile 64x32
    int b = blockIdx.z;
    int iBase = blockIdx.y * 128, jBase = blockIdx.x * 128;

    const bf16* a0h = A0h + (size_t)b * sA;
    const bf16* a0l = A0l + (size_t)b * sA;
    const bf16* a1h = A1h + (size_t)b * sA;
    const bf16* a1l = A1l + (size_t)b * sA;
    const bf16* a2h = A2h + (size_t)b * sA;
    const bf16* a2l = A2l + (size_t)b * sA;
    const bf16* bhp = Bh + (size_t)b * sB;
    const bf16* blp = Bl + (size_t)b * sB;

    float acc[4][4][4];
    #pragma unroll
    for (int i = 0; i < 4; i++)
        #pragma unroll
        for (int j = 0; j < 4; j++)
            #pragma unroll
            for (int k = 0; k < 4; k++) acc[i][j][k] = 0.f;

    int nk = (K + 31) >> 5;
    bool vec = ((K & 31) == 0) && ((Kseg & 31) == 0);
    int Kseg2 = 2 * Kseg;

    // ---- hoisted per-thread load invariants (32-bit; all offsets < 2^31) ----
    int rA  = tid >> 2;                       // row within group
    int ccA = (tid & 3) * 8;                  // k-element offset of this 16B chunk
    int aRow0 = (iBase + rA) * Kseg;
    int aRow1 = (iBase + rA + 64) * Kseg;
    int gn0 = jBase + rA, gn1 = jBase + rA + 64;
    int ok0 = (gn0 < Nv) ? 16 : 0, ok1 = (gn1 < Nv) ? 16 : 0;
    int bRow0 = (ok0 ? gn0 : 0) * K;
    int bRow1 = (ok1 ? gn1 : 0) * K;
    uint32_t so0 = (uint32_t)(rA * PITCH + (tid & 3) * 16);
    uint32_t so1 = so0 + (uint32_t)(64 * PITCH);

    auto load_vec = [&](int stg, int kc0) {
        uint32_t base = sb + stg * STAGE;
        int kg = kc0 + ccA;
        int seg = (kg >= Kseg) + (kg >= Kseg2);       // comparison-based, no IDIV
        const bf16* ph = (seg == 0) ? a0h : ((seg == 1) ? a1h : a2h);
        const bf16* pl = (seg == 0) ? a0l : ((seg == 1) ? a1l : a2l);
        int kloc = kg - seg * Kseg;
        // group 0 (rows 0..63)
        cpa16(base + so0,             ph + (aRow0 + kloc), 16);
        cpa16(base + so0 + TILEB,     pl + (aRow0 + kloc), 16);
        cpa16(base + so0 + 2 * TILEB, bhp + (bRow0 + kg), ok0);
        cpa16(base + so0 + 3 * TILEB, blp + (bRow0 + kg), ok0);
        // group 1 (rows 64..127)
        cpa16(base + so1,             ph + (aRow1 + kloc), 16);
        cpa16(base + so1 + TILEB,     pl + (aRow1 + kloc), 16);
        cpa16(base + so1 + 2 * TILEB, bhp + (bRow1 + kg), ok1);
        cpa16(base + so1 + 3 * TILEB, blp + (bRow1 + kg), ok1);
    };

    auto compute = [&](int stg) {
        uint32_t base = sb + stg * STAGE;
        #pragma unroll
        for (int ks = 0; ks < 2; ks++) {
            int kk = ks * 16;
            uint32_t ah[4][4], al[4][4];
            #pragma unroll
            for (int i = 0; i < 4; i++) {
                int row = wm * 64 + i * 16 + (lane & 15);
                uint32_t ca = base + (uint32_t)(row * PITCH + ((lane >> 4) * 8 + kk) * 2);
                ldm4(ah[i], ca);
                ldm4(al[i], ca + TILEB);
            }
            uint32_t bh[4][2], bl[4][2];
            #pragma unroll
            for (int jj = 0; jj < 2; jj++) {
                int rn = wn * 32 + jj * 16 + (lane & 7) + ((lane >> 4) & 1) * 8;
                uint32_t cb = base + 2 * TILEB +
                              (uint32_t)(rn * PITCH + (kk + ((lane >> 3) & 1) * 8) * 2);
                uint32_t t4[4];
                ldm4(t4, cb);
                bh[jj*2][0] = t4[0]; bh[jj*2][1] = t4[1];
                bh[jj*2+1][0] = t4[2]; bh[jj*2+1][1] = t4[3];
                ldm4(t4, cb + TILEB);
                bl[jj*2][0] = t4[0]; bl[jj*2][1] = t4[1];
                bl[jj*2+1][0] = t4[2]; bl[jj*2+1][1] = t4[3];
            }
            #pragma unroll
            for (int i = 0; i < 4; i++)
                #pragma unroll
                for (int j = 0; j < 4; j++) {
                    mma_bf16(acc[i][j], ah[i], bh[j]);   // hi*hi
                    mma_bf16(acc[i][j], ah[i], bl[j]);   // hi*lo
                    mma_bf16(acc[i][j], al[i], bh[j]);   // lo*hi
                }
        }
    };

    if (vec) {
        // proven pipeline: load(i+1); commit; wait1; sync; compute(i); sync
        load_vec(0, 0); CP_COMMIT();
        for (int i = 0; i < nk; i++) {
            if (i + 1 < nk) { load_vec((i + 1) & 1, (i + 1) * 32); CP_COMMIT(); CP_WAIT1(); }
            else            { CP_WAIT0(); }
            __syncthreads();
            compute(i & 1);
            __syncthreads();
        }
    } else {
        // tiny-K path (layer 1 only: K=6 or K=18)
        for (int c = tid; c < STAGE / 16; c += 256) *(uint4*)(sm + (size_t)c * 16) = make_uint4(0,0,0,0);
        __syncthreads();
        for (int i = 0; i < nk; i++) {
            for (int idx = tid; idx < 128 * 32; idx += 256) {
                int r = idx >> 5, kc = idx & 31;
                int kg = i * 32 + kc;
                uint32_t so = (uint32_t)(r * PITCH + kc * 2);
                if (kg < K) {
                    int seg = (kg >= Kseg) + (kg >= Kseg2);
                    int kkk = kg - seg * Kseg;
                    const bf16* ph = (seg == 0) ? a0h : ((seg == 1) ? a1h : a2h);
                    const bf16* pl = (seg == 0) ? a0l : ((seg == 1) ? a1l : a2l);
                    *(bf16*)(sm + so)          = ph[(size_t)(iBase + r) * Kseg + kkk];
                    *(bf16*)(sm + so + TILEB)  = pl[(size_t)(iBase + r) * Kseg + kkk];
                    int gn = jBase + r;
                    if (gn < Nv) {
                        *(bf16*)(sm + so + 2 * TILEB) = bhp[(size_t)gn * K + kg];
                        *(bf16*)(sm + so + 3 * TILEB) = blp[(size_t)gn * K + kg];
                    }
                }
            }
            __syncthreads();
            compute(0);
            __syncthreads();
            if (i + 1 < nk) {
                for (int c = tid; c < STAGE / 16; c += 256) *(uint4*)(sm + (size_t)c * 16) = make_uint4(0,0,0,0);
                __syncthreads();
            }
        }
    }

    // ---- epilogue (fused: fp32 / split bf16 / transposed split / symmetric mirror) ----
    int g = lane >> 2, t = lane & 3;
    float* Cb  = Cf  ? Cf  + (size_t)b * sC : nullptr;
    bf16* Chb  = Ch  ? Ch  + (size_t)b * sC : nullptr;
    bf16* Clb  = Cl  ? Cl  + (size_t)b * sC : nullptr;
    bf16* Cthb = Cth ? Cth + (size_t)b * sT : nullptr;
    bf16* Ctlb = Ctl ? Ctl + (size_t)b * sT : nullptr;
    bool mirror = (MODE == 1) && (blockIdx.x < blockIdx.y);
    #pragma unroll
    for (int i = 0; i < 4; i++) {
        #pragma unroll
        for (int rr = 0; rr < 2; rr++) {
            int row = iBase + wm * 64 + i * 16 + g + rr * 8;   // M is multiple of 128
            float sqi = (MODE == 1) ? sqv[b * N_ + row] : 0.f;
            #pragma unroll
            for (int j = 0; j < 4; j++) {
                int col = jBase + wn * 32 + j * 8 + 2 * t;
                #pragma unroll
                for (int cc = 0; cc < 2; cc++) {
                    int c2 = col + cc;
                    if (c2 < Nv) {
                        float v = acc[i][j][rr * 2 + cc];
                        if (MODE == 1)      v = __expf(2.f * v - sqi - sqv[b * N_ + c2]);
                        else if (MODE == 2) v = 2.f * v - aux[(size_t)b * sC + (size_t)row * Nv + c2];
                        else if (MODE == 3) v = fmaxf(v + bias[c2], 0.f);
                        size_t o = (size_t)row * Nv + c2;
                        if (Cb) {
                            Cb[o] = v;
                            if (mirror) Cb[(size_t)c2 * Nv + row] = v;   // symmetric mirror
                        }
                        if (Chb) {
                            bf16 h = __float2bfloat16(v);
                            bf16 l = __float2bfloat16(v - __bfloat162float(h));
                            Chb[o] = h;
                            Clb[o] = l;
                            if (Cthb) {                                   // fused transpose split
                                size_t ot = (size_t)c2 * N_ + row;
                                Cthb[ot] = h;
                                Ctlb[ot] = l;
                            }
                        }
                    }
                }
            }
        }
    }
}

// ---------------- conversion / elementwise kernels ----------------
__global__ void split_fp32(const float* __restrict__ X, bf16* __restrict__ H, bf16* __restrict__ L, size_t n) {
    size_t i = ((size_t)blockIdx.x * 256 + threadIdx.x) * 4;
    if (i >= n) return;
    float4 v = *(const float4*)(X + i);
    bf16 hv[4], lv[4];
    float vv[4] = {v.x, v.y, v.z, v.w};
    #pragma unroll
    for (int k = 0; k < 4; k++) {
        bf16 h = __float2bfloat16(vv[k]);
        hv[k] = h;
        lv[k] = __float2bfloat16(vv[k] - __bfloat162float(h));
    }
    *(uint2*)(H + i) = *(uint2*)hv;
    *(uint2*)(L + i) = *(uint2*)lv;
}

__global__ void transpose_split(const float* __restrict__ X, bf16* __restrict__ Th, bf16* __restrict__ Tl, int F) {
    __shared__ float tile[32][33];
    int b = blockIdx.z;
    int n0 = blockIdx.x * 32, f0 = blockIdx.y * 32;
    const float* Xb = X + (size_t)b * N_ * F;
    #pragma unroll
    for (int i = 0; i < 32; i += 8) {
        int nn = n0 + threadIdx.y + i, ff = f0 + threadIdx.x;
        if (ff < F) tile[threadIdx.y + i][threadIdx.x] = Xb[(size_t)nn * F + ff];
    }
    __syncthreads();
    bf16* Thb = Th + (size_t)b * F * N_;
    bf16* Tlb = Tl + (size_t)b * F * N_;
    #pragma unroll
    for (int i = 0; i < 32; i += 8) {
        int ff = f0 + threadIdx.y + i, nn = n0 + threadIdx.x;
        if (ff < F) {
            float v = tile[threadIdx.x][threadIdx.y + i];
            bf16 h = __float2bfloat16(v);
            Thb[(size_t)ff * N_ + nn] = h;
            Tlb[(size_t)ff * N_ + nn] = __float2bfloat16(v - __bfloat162float(h));
        }
    }
}

__global__ void wtrans(const float* __restrict__ W, bf16* __restrict__ Th, bf16* __restrict__ Tl, int Fi, int Fo) {
    int kg = blockIdx.x * 32 + threadIdx.x;
    int o  = blockIdx.y * 8 + threadIdx.y;
    int Kt = 3 * Fi;
    if (kg < Kt && o < Fo) {
        int seg = (kg >= Fi) + (kg >= 2 * Fi);
        int kc = kg - seg * Fi;
        float v = W[((size_t)seg * Fi + kc) * Fo + o];
        bf16 h = __float2bfloat16(v);
        Th[(size_t)o * Kt + kg] = h;
        Tl[(size_t)o * Kt + kg] = __float2bfloat16(v - __bfloat162float(h));
    }
}

__global__ void sqnorm(const float* __restrict__ X, float* __restrict__ sq, int F) {
    int row = blockIdx.x * 8 + threadIdx.y;
    const float* r = X + (size_t)row * F;
    float s = 0.f;
    for (int f = threadIdx.x; f < F; f += 32) { float v = r[f]; s += v * v; }
    #pragma unroll
    for (int o = 16; o; o >>= 1) s += __shfl_xor_sync(0xffffffffu, s, o);
    if (threadIdx.x == 0) sq[row] = s;
}

__global__ void rowdeg(const float* __restrict__ A, float* __restrict__ dis) {
    int row = blockIdx.x * 8 + threadIdx.y;
    const float* r = A + (size_t)row * N_;
    float s = 0.f;
    for (int m = threadIdx.x; m < N_; m += 32) s += r[m];
    #pragma unroll
    for (int o = 16; o; o >>= 1) s += __shfl_xor_sync(0xffffffffu, s, o);
    if (threadIdx.x == 0) dis[row] = rsqrtf(s);
}

__global__ void makeL_split(const float* __restrict__ A, const float* __restrict__ dis,
                            bf16* __restrict__ Lh, bf16* __restrict__ Ll) {
    size_t idx = ((size_t)blockIdx.x * 256 + threadIdx.x) * 4;
    int j0 = (int)(idx & (N_ - 1));
    size_t t = idx >> 10;
    int i = (int)(t & (N_ - 1));
    int b = (int)(t >> 10);
    float di = dis[b * N_ + i];
    float4 a = *(const float4*)(A + idx);
    float av[4] = {a.x, a.y, a.z, a.w};
    bf16 hv[4], lv[4];
    #pragma unroll
    for (int k = 0; k < 4; k++) {
        float v = -di * dis[b * N_ + j0 + k] * av[k];
        if (i == j0 + k) v += 1.f;
        bf16 h = __float2bfloat16(v);
        hv[k] = h;
        lv[k] = __float2bfloat16(v - __bfloat162float(h));
    }
    *(uint2*)(Lh + idx) = *(uint2*)hv;
    *(uint2*)(Ll + idx) = *(uint2*)lv;
}

__global__ void maxpool(const float* __restrict__ H, float* __restrict__ out) {
    int f = blockIdx.x * 256 + threadIdx.x;
    int b = blockIdx.y;
    const float* base = H + (size_t)b * N_ * 1024 + f;
    float m = -1e30f;
    for (int n = 0; n < N_; n++) m = fmaxf(m, base[(size_t)n * 1024]);
    out[b * 1024 + f] = m;
}

__global__ void fckernel(const float* __restrict__ in, const float* __restrict__ W,
                         const float* __restrict__ bias, float* __restrict__ out,
                         int K, int Nout, int dorelu) {
    __shared__ float s[1024];
    int b = blockIdx.x;
    for (int i = threadIdx.x; i < K; i += blockDim.x) s[i] = in[(size_t)b * K + i];
    __syncthreads();
    for (int j = threadIdx.x; j < Nout; j += blockDim.x) {
        float acc = bias[j];
        for (int i = 0; i < K; i++) acc = fmaf(s[i], W[(size_t)i * Nout + j], acc);
        if (dorelu) acc = fmaxf(acc, 0.f);
        out[(size_t)b * Nout + j] = acc;
    }
}

// ---------------- host orchestration ----------------
struct Ptrs {
    float *A, *sq, *dis;
    bf16 *Th, *Tl, *T2h, *T2l, *Lh, *Ll, *x1h, *x1l, *x2h, *x2l, *Wh, *Wl;
};

// inH/inL: split of layer input P (already populated). outH/outL: split of H for next layer (may be null).
static void conv_layer(const float* P, bf16* inH, bf16* inL, int Fi, int Fo,
                       const float* W, const float* bias,
                       float* H, bf16* outH, bf16* outL, const Ptrs& p)
{
    dim3 tb32(32, 8);

    transpose_split<<<dim3(32, (Fi + 31) / 32, B_), tb32>>>(P, p.Th, p.Tl, Fi);
    sqnorm<<<B_ * N_ / 8, tb32>>>(P, p.sq, Fi);

    // adjacency: A = exp(2*X*X^T - sq_i - sq_j)  — symmetric: upper-tri CTAs exit, mirror-write
    gemm_mma<1><<<dim3(8, 8, B_), 256, SMEMSZ>>>(
        inH, inL, inH, inL, inH, inL, inH, inL,
        p.A, nullptr, nullptr, nullptr, nullptr,
        N_, N_, Fi, Fi, (long long)N_ * Fi, (long long)N_ * Fi, (long long)N_ * N_, 0,
        p.sq, nullptr, nullptr);

    rowdeg<<<B_ * N_ / 8, tb32>>>(p.A, p.dis);
    makeL_split<<<(unsigned)((size_t)B_ * N_ * N_ / 1024), 256>>>(p.A, p.dis, p.Lh, p.Ll);

    // x1 = L @ x0 : split bf16 (row-major for feature gemm) + fused transposed split (for x2 gemm)
    gemm_mma<0><<<dim3((Fi + 127) / 128, 8, B_), 256, SMEMSZ>>>(
        p.Lh, p.Ll, p.Lh, p.Ll, p.Lh, p.Ll, p.Th, p.Tl,
        nullptr, p.x1h, p.x1l, p.T2h, p.T2l,
        N_, Fi, N_, N_, (long long)N_ * N_, (long long)Fi * N_, (long long)N_ * Fi, (long long)Fi * N_,
        nullptr, nullptr, nullptr);

    // x2 = 2 L @ x1 - x0 : split bf16 only (B operand = fused-transposed x1)
    gemm_mma<2><<<dim3((Fi + 127) / 128, 8, B_), 256, SMEMSZ>>>(
        p.Lh, p.Ll, p.Lh, p.Ll, p.Lh, p.Ll, p.T2h, p.T2l,
        nullptr, p.x2h, p.x2l, nullptr, nullptr,
        N_, Fi, N_, N_, (long long)N_ * N_, (long long)Fi * N_, (long long)N_ * Fi, 0,
        nullptr, P, nullptr);

    wtrans<<<dim3((3 * Fi + 31) / 32, (Fo + 7) / 8), tb32>>>(W, p.Wh, p.Wl, Fi, Fo);

    // H = relu(x0 W0 + x1 W1 + x2 W2 + b); also emit next layer's split
    gemm_mma<3><<<dim3((Fo + 127) / 128, B_ * N_ / 128, 1), 256, SMEMSZ>>>(
        inH, inL, p.x1h, p.x1l, p.x2h, p.x2l, p.Wh, p.Wl,
        H, outH, outL, nullptr, nullptr,
        B_ * N_, Fo, 3 * Fi, Fi, 0, 0, 0, 0,
        nullptr, nullptr, bias);
}

extern "C" void kernel_launch(void* const* d_in, const int* in_sizes, int n_in,
                              void* d_out, int out_size) {
    (void)in_sizes; (void)n_in; (void)out_size;
    const float* x     = (const float*)d_in[0];
    const float* W1    = (const float*)d_in[1];
    const float* b1    = (const float*)d_in[2];
    const float* W2    = (const float*)d_in[3];
    const float* b2    = (const float*)d_in[4];
    const float* W3    = (const float*)d_in[5];
    const float* b3    = (const float*)d_in[6];
    const float* fc1_w = (const float*)d_in[7];
    const float* fc1_b = (const float*)d_in[8];
    const float* fc2_w = (const float*)d_in[9];
    const float* fc2_b = (const float*)d_in[10];
    const float* fc3_w = (const float*)d_in[11];
    const float* fc3_b = (const float*)d_in[12];
    float* out = (float*)d_out;

    cudaFuncSetAttribute(gemm_mma<0>, cudaFuncAttributeMaxDynamicSharedMemorySize, SMEMSZ);
    cudaFuncSetAttribute(gemm_mma<1>, cudaFuncAttributeMaxDynamicSharedMemorySize, SMEMSZ);
    cudaFuncSetAttribute(gemm_mma<2>, cudaFuncAttributeMaxDynamicSharedMemorySize, SMEMSZ);
    cudaFuncSetAttribute(gemm_mma<3>, cudaFuncAttributeMaxDynamicSharedMemorySize, SMEMSZ);

    Ptrs p;
    bf16 *Xh, *Xl, *Yh, *Yl;
    float *H1, *H2, *H3, *pool, *f1, *f2;
    cudaGetSymbolAddress((void**)&p.A,   g_A);
    cudaGetSymbolAddress((void**)&p.sq,  g_sq);
    cudaGetSymbolAddress((void**)&p.dis, g_dis);
    cudaGetSymbolAddress((void**)&Xh,    g_Xh);
    cudaGetSymbolAddress((void**)&Xl,    g_Xl);
    cudaGetSymbolAddress((void**)&Yh,    g_Yh);
    cudaGetSymbolAddress((void**)&Yl,    g_Yl);
    cudaGetSymbolAddress((void**)&p.Th,  g_Th);
    cudaGetSymbolAddress((void**)&p.Tl,  g_Tl);
    cudaGetSymbolAddress((void**)&p.T2h, g_T2h);
    cudaGetSymbolAddress((void**)&p.T2l, g_T2l);
    cudaGetSymbolAddress((void**)&p.Lh,  g_Lh);
    cudaGetSymbolAddress((void**)&p.Ll,  g_Ll);
    cudaGetSymbolAddress((void**)&p.x1h, g_x1h);
    cudaGetSymbolAddress((void**)&p.x1l, g_x1l);
    cudaGetSymbolAddress((void**)&p.x2h, g_x2h);
    cudaGetSymbolAddress((void**)&p.x2l, g_x2l);
    cudaGetSymbolAddress((void**)&p.Wh,  g_Wh);
    cudaGetSymbolAddress((void**)&p.Wl,  g_Wl);
    cudaGetSymbolAddress((void**)&H1,    g_H1);
    cudaGetSymbolAddress((void**)&H2,    g_H2);
    cudaGetSymbolAddress((void**)&H3,    g_H3);
    cudaGetSymbolAddress((void**)&pool,  g_pool);
    cudaGetSymbolAddress((void**)&f1,    g_f1);
    cudaGetSymbolAddress((void**)&f2,    g_f2);

    // layer 1: split the raw input, H1 split -> Y
    split_fp32<<<(unsigned)(((size_t)B_ * N_ * 6 + 1023) / 1024), 256>>>(x, Xh, Xl, (size_t)B_ * N_ * 6);
    conv_layer(x,  Xh, Xl, 6,   128,  W1, b1, H1, Yh, Yl, p);
    // layer 2: input split = Y, H2 split -> X (ping-pong)
    conv_layer(H1, Yh, Yl, 128, 512,  W2, b2, H2, Xh, Xl, p);
    // layer 3: input split = X, no H split needed
    conv_layer(H2, Xh, Xl, 512, 1024, W3, b3, H3, nullptr, nullptr, p);

    maxpool<<<dim3(4, B_), 256>>>(H3, pool);
    fckernel<<<B_, 256>>>(pool, fc1_w, fc1_b, f1, 1024, 512, 1);
    fckernel<<<B_, 256>>>(f1,   fc2_w, fc2_b, f2, 512, 128, 1);
    fckernel<<<B_, 256>>>(f2,   fc3_w, fc3_b, out, 128, 40, 0);
}

// round 14
// speedup vs baseline: 1.8094x; 1.1282x over previous
#include <cuda_runtime.h>
#include <cuda_fp16.h>
#include <math.h>
#include <stdint.h>

#define B_ 32
#define N_ 1024
typedef __half bf16;   // limb type is now fp16 (name kept to minimize diff)

__device__ __forceinline__ bf16 f2l(float v) { return __float2half_rn(v); }
__device__ __forceinline__ float l2f(bf16 v) { return __half2float(v); }

// ---------------- scratch (static device memory; no runtime alloc) ----------------
__device__ __align__(256) float g_A  [(size_t)B_*N_*N_];     // adjacency fp32
__device__ __align__(256) bf16  g_Lh [(size_t)B_*N_*N_];     // Laplacian hi
__device__ __align__(256) bf16  g_Ll [(size_t)B_*N_*N_];     // Laplacian lo
__device__ __align__(256) bf16  g_Xh [(size_t)B_*N_*512];    // layer input split (ping)
__device__ __align__(256) bf16  g_Xl [(size_t)B_*N_*512];
__device__ __align__(256) bf16  g_Yh [(size_t)B_*N_*512];    // layer input split (pong)
__device__ __align__(256) bf16  g_Yl [(size_t)B_*N_*512];
__device__ __align__(256) bf16  g_Th [(size_t)B_*512*N_];    // transposed layer-input split
__device__ __align__(256) bf16  g_Tl [(size_t)B_*512*N_];
__device__ __align__(256) bf16  g_T2h[(size_t)B_*512*N_];    // transposed x1 split (epilogue-fused)
__device__ __align__(256) bf16  g_T2l[(size_t)B_*512*N_];
__device__ __align__(256) bf16  g_x1h[(size_t)B_*N_*512];
__device__ __align__(256) bf16  g_x2h[(size_t)B_*N_*512];
__device__ __align__(256) float g_H1 [(size_t)B_*N_*128];
__device__ __align__(256) float g_H2 [(size_t)B_*N_*512];
__device__ __align__(256) float g_H3 [(size_t)B_*N_*1024];
__device__ __align__(256) bf16  g_Wh [1024*1536];
__device__ __align__(256) bf16  g_Wl [1024*1536];
__device__ float g_sq [B_*N_];
__device__ float g_dis[B_*N_];
__device__ float g_pool[B_*1024];
__device__ float g_f1 [B_*512];
__device__ float g_f2 [B_*128];

// ---------------- PTX helpers ----------------
__device__ __forceinline__ uint32_t smem_u32(const void* p) {
    uint32_t a;
    asm("{ .reg .u64 t; cvta.to.shared.u64 t, %1; cvt.u32.u64 %0, t; }" : "=r"(a) : "l"(p));
    return a;
}
__device__ __forceinline__ void cpa16(uint32_t s, const void* g, int sz) {
    asm volatile("cp.async.cg.shared.global [%0], [%1], 16, %2;" :: "r"(s), "l"(g), "r"(sz));
}
#define CP_COMMIT() asm volatile("cp.async.commit_group;")
#define CP_WAIT0()  asm volatile("cp.async.wait_group 0;")
#define CP_WAIT1()  asm volatile("cp.async.wait_group 1;")

__device__ __forceinline__ void ldm4(uint32_t* r, uint32_t a) {
    asm volatile("ldmatrix.sync.aligned.m8n8.x4.shared.b16 {%0,%1,%2,%3}, [%4];"
        : "=r"(r[0]), "=r"(r[1]), "=r"(r[2]), "=r"(r[3]) : "r"(a));
}
__device__ __forceinline__ void mma_f16(float* d, const uint32_t* a, const uint32_t* b) {
    asm volatile("mma.sync.aligned.m16n8k16.row.col.f32.f16.f16.f32 "
        "{%0,%1,%2,%3},{%4,%5,%6,%7},{%8,%9},{%0,%1,%2,%3};"
        : "+f"(d[0]), "+f"(d[1]), "+f"(d[2]), "+f"(d[3])
        : "r"(a[0]), "r"(a[1]), "r"(a[2]), "r"(a[3]), "r"(b[0]), "r"(b[1]));
}

// smem tile: 128 rows x 32 fp16 cols, pitch 80B (64B data + 16B pad; 5r mod 8 permutation
// => conflict-free ldmatrix). K-chunk 32, double-buffered => 80KB => 2 CTAs/SM.
#define PITCH  80
#define TILEB  (128 * PITCH)     /* 10240 bytes per operand-limb tile */
#define STAGE  (4 * TILEB)       /* Ah | Al | Bh | Bl = 40960 */
#define SMEMSZ (2 * STAGE)       /* double buffered = 81920 */

// ---------------- split-fp16 HMMA GEMM ----------------
// C[M,Nv] = sum_seg A_seg[M,Kseg] * B[Nv,K]^T  (A row-major, B K-major [Nv,K])
// MODE 0: plain   MODE 1: __expf(2v - sq_i - sq_j), SYMMETRIC (bx<=by only, mirror write)
// MODE 2: 2v - aux   MODE 3: relu(v + bias), 2-PRODUCT (A-lo term dropped; fp16 limbs make it ~2^-12)
// Writes fp32 to Cf, split fp16 to Ch/Cl, transposed split to Cth/Ctl (each if non-null).
template<int MODE>
__global__ __launch_bounds__(256, 2) void gemm_mma(
    const bf16* A0h, const bf16* A0l, const bf16* A1h, const bf16* A1l,
    const bf16* A2h, const bf16* A2l,
    const bf16* Bh, const bf16* Bl,
    float* Cf, bf16* Ch, bf16* Cl, bf16* Cth, bf16* Ctl,
    int M, int Nv, int K, int Kseg,
    long long sA, long long sB, long long sC, long long sT,
    const float* sqv, const float* aux, const float* bias)
{
    if (MODE == 1 && blockIdx.x > blockIdx.y) return;   // symmetric: skip upper-tri blocks

    extern __shared__ char sm[];
    uint32_t sb = smem_u32(sm);
    int tid = threadIdx.x, lane = tid & 31, w = tid >> 5;
    int wm = w & 1, wn = w >> 1;          // 2 x 4 warp grid, warp tile 64x32
    int b = blockIdx.z;
    int iBase = blockIdx.y * 128, jBase = blockIdx.x * 128;

    const bf16* a0h = A0h + (size_t)b * sA;
    const bf16* a0l = A0l + (size_t)b * sA;
    const bf16* a1h = A1h + (size_t)b * sA;
    const bf16* a1l = A1l + (size_t)b * sA;
    const bf16* a2h = A2h + (size_t)b * sA;
    const bf16* a2l = A2l + (size_t)b * sA;
    const bf16* bhp = Bh + (size_t)b * sB;
    const bf16* blp = Bl + (size_t)b * sB;

    float acc[4][4][4];
    #pragma unroll
    for (int i = 0; i < 4; i++)
        #pragma unroll
        for (int j = 0; j < 4; j++)
            #pragma unroll
            for (int k = 0; k < 4; k++) acc[i][j][k] = 0.f;

    int nk = (K + 31) >> 5;
    bool vec = ((K & 31) == 0) && ((Kseg & 31) == 0);
    int Kseg2 = 2 * Kseg;

    // ---- hoisted per-thread load invariants (32-bit; all offsets < 2^31) ----
    int rA  = tid >> 2;                       // row within group
    int ccA = (tid & 3) * 8;                  // k-element offset of this 16B chunk
    int aRow0 = (iBase + rA) * Kseg;
    int aRow1 = (iBase + rA + 64) * Kseg;
    int gn0 = jBase + rA, gn1 = jBase + rA + 64;
    int ok0 = (gn0 < Nv) ? 16 : 0, ok1 = (gn1 < Nv) ? 16 : 0;
    int bRow0 = (ok0 ? gn0 : 0) * K;
    int bRow1 = (ok1 ? gn1 : 0) * K;
    uint32_t so0 = (uint32_t)(rA * PITCH + (tid & 3) * 16);
    uint32_t so1 = so0 + (uint32_t)(64 * PITCH);

    auto load_vec = [&](int stg, int kc0) {
        uint32_t base = sb + stg * STAGE;
        int kg = kc0 + ccA;
        int seg = (kg >= Kseg) + (kg >= Kseg2);       // comparison-based, no IDIV
        const bf16* ph = (seg == 0) ? a0h : ((seg == 1) ? a1h : a2h);
        int kloc = kg - seg * Kseg;
        // group 0 (rows 0..63)
        cpa16(base + so0,             ph + (aRow0 + kloc), 16);
        cpa16(base + so0 + 2 * TILEB, bhp + (bRow0 + kg), ok0);
        cpa16(base + so0 + 3 * TILEB, blp + (bRow0 + kg), ok0);
        // group 1 (rows 64..127)
        cpa16(base + so1,             ph + (aRow1 + kloc), 16);
        cpa16(base + so1 + 2 * TILEB, bhp + (bRow1 + kg), ok1);
        cpa16(base + so1 + 3 * TILEB, blp + (bRow1 + kg), ok1);
        if (MODE != 3) {               // A-lo limb only needed for 3-product modes
            const bf16* pl = (seg == 0) ? a0l : ((seg == 1) ? a1l : a2l);
            cpa16(base + so0 + TILEB, pl + (aRow0 + kloc), 16);
            cpa16(base + so1 + TILEB, pl + (aRow1 + kloc), 16);
        }
    };

    auto compute = [&](int stg) {
        uint32_t base = sb + stg * STAGE;
        #pragma unroll
        for (int ks = 0; ks < 2; ks++) {
            int kk = ks * 16;
            uint32_t ah[4][4], al[4][4];
            #pragma unroll
            for (int i = 0; i < 4; i++) {
                int row = wm * 64 + i * 16 + (lane & 15);
                uint32_t ca = base + (uint32_t)(row * PITCH + ((lane >> 4) * 8 + kk) * 2);
                ldm4(ah[i], ca);
                if (MODE != 3) ldm4(al[i], ca + TILEB);
            }
            uint32_t bh[4][2], bl[4][2];
            #pragma unroll
            for (int jj = 0; jj < 2; jj++) {
                int rn = wn * 32 + jj * 16 + (lane & 7) + ((lane >> 4) & 1) * 8;
                uint32_t cb = base + 2 * TILEB +
                              (uint32_t)(rn * PITCH + (kk + ((lane >> 3) & 1) * 8) * 2);
                uint32_t t4[4];
                ldm4(t4, cb);
                bh[jj*2][0] = t4[0]; bh[jj*2][1] = t4[1];
                bh[jj*2+1][0] = t4[2]; bh[jj*2+1][1] = t4[3];
                ldm4(t4, cb + TILEB);
                bl[jj*2][0] = t4[0]; bl[jj*2][1] = t4[1];
                bl[jj*2+1][0] = t4[2]; bl[jj*2+1][1] = t4[3];
            }
            #pragma unroll
            for (int i = 0; i < 4; i++)
                #pragma unroll
                for (int j = 0; j < 4; j++) {
                    mma_f16(acc[i][j], ah[i], bh[j]);                   // hi*hi
                    mma_f16(acc[i][j], ah[i], bl[j]);                   // hi*lo
                    if (MODE != 3) mma_f16(acc[i][j], al[i], bh[j]);    // lo*hi (3-prod modes)
                }
        }
    };

    if (vec) {
        // proven pipeline: load(i+1); commit; wait1; sync; compute(i); sync
        load_vec(0, 0); CP_COMMIT();
        for (int i = 0; i < nk; i++) {
            if (i + 1 < nk) { load_vec((i + 1) & 1, (i + 1) * 32); CP_COMMIT(); CP_WAIT1(); }
            else            { CP_WAIT0(); }
            __syncthreads();
            compute(i & 1);
            __syncthreads();
        }
    } else {
        // tiny-K path (layer 1 only: K=6 or K=18)
        for (int c = tid; c < STAGE / 16; c += 256) *(uint4*)(sm + (size_t)c * 16) = make_uint4(0,0,0,0);
        __syncthreads();
        for (int i = 0; i < nk; i++) {
            for (int idx = tid; idx < 128 * 32; idx += 256) {
                int r = idx >> 5, kc = idx & 31;
                int kg = i * 32 + kc;
                uint32_t so = (uint32_t)(r * PITCH + kc * 2);
                if (kg < K) {
                    int seg = (kg >= Kseg) + (kg >= Kseg2);
                    int kkk = kg - seg * Kseg;
                    const bf16* ph = (seg == 0) ? a0h : ((seg == 1) ? a1h : a2h);
                    *(bf16*)(sm + so) = ph[(size_t)(iBase + r) * Kseg + kkk];
                    if (MODE != 3) {
                        const bf16* pl = (seg == 0) ? a0l : ((seg == 1) ? a1l : a2l);
                        *(bf16*)(sm + so + TILEB) = pl[(size_t)(iBase + r) * Kseg + kkk];
                    }
                    int gn = jBase + r;
                    if (gn < Nv) {
                        *(bf16*)(sm + so + 2 * TILEB) = bhp[(size_t)gn * K + kg];
                        *(bf16*)(sm + so + 3 * TILEB) = blp[(size_t)gn * K + kg];
                    }
                }
            }
            __syncthreads();
            compute(0);
            __syncthreads();
            if (i + 1 < nk) {
                for (int c = tid; c < STAGE / 16; c += 256) *(uint4*)(sm + (size_t)c * 16) = make_uint4(0,0,0,0);
                __syncthreads();
            }
        }
    }

    // ---- epilogue (fused: fp32 / split fp16 / transposed split / symmetric mirror) ----
    int g = lane >> 2, t = lane & 3;
    float* Cb  = Cf  ? Cf  + (size_t)b * sC : nullptr;
    bf16* Chb  = Ch  ? Ch  + (size_t)b * sC : nullptr;
    bf16* Clb  = Cl  ? Cl  + (size_t)b * sC : nullptr;
    bf16* Cthb = Cth ? Cth + (size_t)b * sT : nullptr;
    bf16* Ctlb = Ctl ? Ctl + (size_t)b * sT : nullptr;
    bool mirror = (MODE == 1) && (blockIdx.x < blockIdx.y);
    #pragma unroll
    for (int i = 0; i < 4; i++) {
        #pragma unroll
        for (int rr = 0; rr < 2; rr++) {
            int row = iBase + wm * 64 + i * 16 + g + rr * 8;   // M is multiple of 128
            float sqi = (MODE == 1) ? sqv[b * N_ + row] : 0.f;
            #pragma unroll
            for (int j = 0; j < 4; j++) {
                int col = jBase + wn * 32 + j * 8 + 2 * t;
                #pragma unroll
                for (int cc = 0; cc < 2; cc++) {
                    int c2 = col + cc;
                    if (c2 < Nv) {
                        float v = acc[i][j][rr * 2 + cc];
                        if (MODE == 1)      v = __expf(2.f * v - sqi - sqv[b * N_ + c2]);
                        else if (MODE == 2) v = 2.f * v - aux[(size_t)b * sC + (size_t)row * Nv + c2];
                        else if (MODE == 3) v = fmaxf(v + bias[c2], 0.f);
                        size_t o = (size_t)row * Nv + c2;
                        if (Cb) {
                            Cb[o] = v;
                            if (mirror) Cb[(size_t)c2 * Nv + row] = v;   // symmetric mirror
                        }
                        if (Chb) {
                            bf16 h = f2l(v);
                            Chb[o] = h;
                            bf16 l = f2l(v - l2f(h));
                            if (Clb) Clb[o] = l;
                            if (Cthb) {                                   // fused transpose split
                                size_t ot = (size_t)c2 * N_ + row;
                                Cthb[ot] = h;
                                Ctlb[ot] = l;
                            }
                        }
                    }
                }
            }
        }
    }
}

// ---------------- conversion / elementwise kernels ----------------
__global__ void split_fp32(const float* __restrict__ X, bf16* __restrict__ H, bf16* __restrict__ L, size_t n) {
    size_t i = ((size_t)blockIdx.x * 256 + threadIdx.x) * 4;
    if (i >= n) return;
    float4 v = *(const float4*)(X + i);
    bf16 hv[4], lv[4];
    float vv[4] = {v.x, v.y, v.z, v.w};
    #pragma unroll
    for (int k = 0; k < 4; k++) {
        bf16 h = f2l(vv[k]);
        hv[k] = h;
        lv[k] = f2l(vv[k] - l2f(h));
    }
    *(uint2*)(H + i) = *(uint2*)hv;
    *(uint2*)(L + i) = *(uint2*)lv;
}

__global__ void transpose_split(const float* __restrict__ X, bf16* __restrict__ Th, bf16* __restrict__ Tl, int F) {
    __shared__ float tile[32][33];
    int b = blockIdx.z;
    int n0 = blockIdx.x * 32, f0 = blockIdx.y * 32;
    const float* Xb = X + (size_t)b * N_ * F;
    #pragma unroll
    for (int i = 0; i < 32; i += 8) {
        int nn = n0 + threadIdx.y + i, ff = f0 + threadIdx.x;
        if (ff < F) tile[threadIdx.y + i][threadIdx.x] = Xb[(size_t)nn * F + ff];
    }
    __syncthreads();
    bf16* Thb = Th + (size_t)b * F * N_;
    bf16* Tlb = Tl + (size_t)b * F * N_;
    #pragma unroll
    for (int i = 0; i < 32; i += 8) {
        int ff = f0 + threadIdx.y + i, nn = n0 + threadIdx.x;
        if (ff < F) {
            float v = tile[threadIdx.x][threadIdx.y + i];
            bf16 h = f2l(v);
            Thb[(size_t)ff * N_ + nn] = h;
            Tlb[(size_t)ff * N_ + nn] = f2l(v - l2f(h));
        }
    }
}

__global__ void wtrans(const float* __restrict__ W, bf16* __restrict__ Th, bf16* __restrict__ Tl, int Fi, int Fo) {
    int kg = blockIdx.x * 32 + threadIdx.x;
    int o  = blockIdx.y * 8 + threadIdx.y;
    int Kt = 3 * Fi;
    if (kg < Kt && o < Fo) {
        int seg = (kg >= Fi) + (kg >= 2 * Fi);
        int kc = kg - seg * Fi;
        float v = W[((size_t)seg * Fi + kc) * Fo + o];
        bf16 h = f2l(v);
        Th[(size_t)o * Kt + kg] = h;
        Tl[(size_t)o * Kt + kg] = f2l(v - l2f(h));
    }
}

__global__ void sqnorm(const float* __restrict__ X, float* __restrict__ sq, int F) {
    int row = blockIdx.x * 8 + threadIdx.y;
    const float* r = X + (size_t)row * F;
    float s = 0.f;
    for (int f = threadIdx.x; f < F; f += 32) { float v = r[f]; s += v * v; }
    #pragma unroll
    for (int o = 16; o; o >>= 1) s += __shfl_xor_sync(0xffffffffu, s, o);
    if (threadIdx.x == 0) sq[row] = s;
}

__global__ void rowdeg(const float* __restrict__ A, float* __restrict__ dis) {
    int row = blockIdx.x * 8 + threadIdx.y;
    const float* r = A + (size_t)row * N_;
    float s = 0.f;
    for (int m = threadIdx.x; m < N_; m += 32) s += r[m];
    #pragma unroll
    for (int o = 16; o; o >>= 1) s += __shfl_xor_sync(0xffffffffu, s, o);
    if (threadIdx.x == 0) dis[row] = rsqrtf(s);
}

__global__ void makeL_split(const float* __restrict__ A, const float* __restrict__ dis,
                            bf16* __restrict__ Lh, bf16* __restrict__ Ll) {
    size_t idx = ((size_t)blockIdx.x * 256 + threadIdx.x) * 4;
    int j0 = (int)(idx & (N_ - 1));
    size_t t = idx >> 10;
    int i = (int)(t & (N_ - 1));
    int b = (int)(t >> 10);
    float di = dis[b * N_ + i];
    float4 a = *(const float4*)(A + idx);
    float av[4] = {a.x, a.y, a.z, a.w};
    bf16 hv[4], lv[4];
    #pragma unroll
    for (int k = 0; k < 4; k++) {
        float v = -di * dis[b * N_ + j0 + k] * av[k];
        if (i == j0 + k) v += 1.f;
        bf16 h = f2l(v);
        hv[k] = h;
        lv[k] = f2l(v - l2f(h));
    }
    *(uint2*)(Lh + idx) = *(uint2*)hv;
    *(uint2*)(Ll + idx) = *(uint2*)lv;
}

__global__ void maxpool(const float* __restrict__ H, float* __restrict__ out) {
    int f = blockIdx.x * 256 + threadIdx.x;
    int b = blockIdx.y;
    const float* base = H + (size_t)b * N_ * 1024 + f;
    float m = -1e30f;
    for (int n = 0; n < N_; n++) m = fmaxf(m, base[(size_t)n * 1024]);
    out[b * 1024 + f] = m;
}

__global__ void fckernel(const float* __restrict__ in, const float* __restrict__ W,
                         const float* __restrict__ bias, float* __restrict__ out,
                         int K, int Nout, int dorelu) {
    __shared__ float s[1024];
    int b = blockIdx.x;
    for (int i = threadIdx.x; i < K; i += blockDim.x) s[i] = in[(size_t)b * K + i];
    __syncthreads();
    for (int j = threadIdx.x; j < Nout; j += blockDim.x) {
        float acc = bias[j];
        for (int i = 0; i < K; i++) acc = fmaf(s[i], W[(size_t)i * Nout + j], acc);
        if (dorelu) acc = fmaxf(acc, 0.f);
        out[(size_t)b * Nout + j] = acc;
    }
}

// ---------------- host orchestration ----------------
struct Ptrs {
    float *A, *sq, *dis;
    bf16 *Th, *Tl, *T2h, *T2l, *Lh, *Ll, *x1h, *x2h, *Wh, *Wl;
};

// inH/inL: split of layer input P (already populated). outH/outL: split of H for next layer (may be null).
static void conv_layer(const float* P, bf16* inH, bf16* inL, int Fi, int Fo,
                       const float* W, const float* bias,
                       float* H, bf16* outH, bf16* outL, const Ptrs& p)
{
    dim3 tb32(32, 8);

    transpose_split<<<dim3(32, (Fi + 31) / 32, B_), tb32>>>(P, p.Th, p.Tl, Fi);
    sqnorm<<<B_ * N_ / 8, tb32>>>(P, p.sq, Fi);

    // adjacency: A = exp(2*X*X^T - sq_i - sq_j)  — symmetric: upper-tri CTAs exit, mirror-write
    gemm_mma<1><<<dim3(8, 8, B_), 256, SMEMSZ>>>(
        inH, inL, inH, inL, inH, inL, inH, inL,
        p.A, nullptr, nullptr, nullptr, nullptr,
        N_, N_, Fi, Fi, (long long)N_ * Fi, (long long)N_ * Fi, (long long)N_ * N_, 0,
        p.sq, nullptr, nullptr);

    rowdeg<<<B_ * N_ / 8, tb32>>>(p.A, p.dis);
    makeL_split<<<(unsigned)((size_t)B_ * N_ * N_ / 1024), 256>>>(p.A, p.dis, p.Lh, p.Ll);

    // x1 = L @ x0 : split fp16 hi (row-major, feature gemm A1) + fused transposed split (x2 gemm B)
    gemm_mma<0><<<dim3((Fi + 127) / 128, 8, B_), 256, SMEMSZ>>>(
        p.Lh, p.Ll, p.Lh, p.Ll, p.Lh, p.Ll, p.Th, p.Tl,
        nullptr, p.x1h, nullptr, p.T2h, p.T2l,
        N_, Fi, N_, N_, (long long)N_ * N_, (long long)Fi * N_, (long long)N_ * Fi, (long long)Fi * N_,
        nullptr, nullptr, nullptr);

    // x2 = 2 L @ x1 - x0 : hi split only (feature gemm A2; 2-product there needs no lo)
    gemm_mma<2><<<dim3((Fi + 127) / 128, 8, B_), 256, SMEMSZ>>>(
        p.Lh, p.Ll, p.Lh, p.Ll, p.Lh, p.Ll, p.T2h, p.T2l,
        nullptr, p.x2h, nullptr, nullptr, nullptr,
        N_, Fi, N_, N_, (long long)N_ * N_, (long long)Fi * N_, (long long)N_ * Fi, 0,
        nullptr, P, nullptr);

    wtrans<<<dim3((3 * Fi + 31) / 32, (Fo + 7) / 8), tb32>>>(W, p.Wh, p.Wl, Fi, Fo);

    // H = relu(x0 W0 + x1 W1 + x2 W2 + b); 2-product (A-hi only); emits next layer's split
    gemm_mma<3><<<dim3((Fo + 127) / 128, B_ * N_ / 128, 1), 256, SMEMSZ>>>(
        inH, inH, p.x1h, p.x1h, p.x2h, p.x2h, p.Wh, p.Wl,
        H, outH, outL, nullptr, nullptr,
        B_ * N_, Fo, 3 * Fi, Fi, 0, 0, 0, 0,
        nullptr, nullptr, bias);
}

extern "C" void kernel_launch(void* const* d_in, const int* in_sizes, int n_in,
                              void* d_out, int out_size) {
    (void)in_sizes; (void)n_in; (void)out_size;
    const float* x     = (const float*)d_in[0];
    const float* W1    = (const float*)d_in[1];
    const float* b1    = (const float*)d_in[2];
    const float* W2    = (const float*)d_in[3];
    const float* b2    = (const float*)d_in[4];
    const float* W3    = (const float*)d_in[5];
    const float* b3    = (const float*)d_in[6];
    const float* fc1_w = (const float*)d_in[7];
    const float* fc1_b = (const float*)d_in[8];
    const float* fc2_w = (const float*)d_in[9];
    const float* fc2_b = (const float*)d_in[10];
    const float* fc3_w = (const float*)d_in[11];
    const float* fc3_b = (const float*)d_in[12];
    float* out = (float*)d_out;

    cudaFuncSetAttribute(gemm_mma<0>, cudaFuncAttributeMaxDynamicSharedMemorySize, SMEMSZ);
    cudaFuncSetAttribute(gemm_mma<1>, cudaFuncAttributeMaxDynamicSharedMemorySize, SMEMSZ);
    cudaFuncSetAttribute(gemm_mma<2>, cudaFuncAttributeMaxDynamicSharedMemorySize, SMEMSZ);
    cudaFuncSetAttribute(gemm_mma<3>, cudaFuncAttributeMaxDynamicSharedMemorySize, SMEMSZ);

    Ptrs p;
    bf16 *Xh, *Xl, *Yh, *Yl;
    float *H1, *H2, *H3, *pool, *f1, *f2;
    cudaGetSymbolAddress((void**)&p.A,   g_A);
    cudaGetSymbolAddress((void**)&p.sq,  g_sq);
    cudaGetSymbolAddress((void**)&p.dis, g_dis);
    cudaGetSymbolAddress((void**)&Xh,    g_Xh);
    cudaGetSymbolAddress((void**)&Xl,    g_Xl);
    cudaGetSymbolAddress((void**)&Yh,    g_Yh);
    cudaGetSymbolAddress((void**)&Yl,    g_Yl);
    cudaGetSymbolAddress((void**)&p.Th,  g_Th);
    cudaGetSymbolAddress((void**)&p.Tl,  g_Tl);
    cudaGetSymbolAddress((void**)&p.T2h, g_T2h);
    cudaGetSymbolAddress((void**)&p.T2l, g_T2l);
    cudaGetSymbolAddress((void**)&p.Lh,  g_Lh);
    cudaGetSymbolAddress((void**)&p.Ll,  g_Ll);
    cudaGetSymbolAddress((void**)&p.x1h, g_x1h);
    cudaGetSymbolAddress((void**)&p.x2h, g_x2h);
    cudaGetSymbolAddress((void**)&p.Wh,  g_Wh);
    cudaGetSymbolAddress((void**)&p.Wl,  g_Wl);
    cudaGetSymbolAddress((void**)&H1,    g_H1);
    cudaGetSymbolAddress((void**)&H2,    g_H2);
    cudaGetSymbolAddress((void**)&H3,    g_H3);
    cudaGetSymbolAddress((void**)&pool,  g_pool);
    cudaGetSymbolAddress((void**)&f1,    g_f1);
    cudaGetSymbolAddress((void**)&f2,    g_f2);

    // layer 1: split the raw input, H1 split -> Y
    split_fp32<<<(unsigned)(((size_t)B_ * N_ * 6 + 1023) / 1024), 256>>>(x, Xh, Xl, (size_t)B_ * N_ * 6);
    conv_layer(x,  Xh, Xl, 6,   128,  W1, b1, H1, Yh, Yl, p);
    // layer 2: input split = Y, H2 split -> X (ping-pong)
    conv_layer(H1, Yh, Yl, 128, 512,  W2, b2, H2, Xh, Xl, p);
    // layer 3: input split = X, no H split needed
    conv_layer(H2, Xh, Xl, 512, 1024, W3, b3, H3, nullptr, nullptr, p);

    maxpool<<<dim3(4, B_), 256>>>(H3, pool);
    fckernel<<<B_, 256>>>(pool, fc1_w, fc1_b, f1, 1024, 512, 1);
    fckernel<<<B_, 256>>>(f1,   fc2_w, fc2_b, f2, 512, 128, 1);
    fckernel<<<B_, 256>>>(f2,   fc3_w, fc3_b, out, 128, 40, 0);
}

// round 15
// speedup vs baseline: 2.0302x; 1.1221x over previous
#include <cuda_runtime.h>
#include <cuda_fp16.h>
#include <math.h>
#include <stdint.h>

#define B_ 32
#define N_ 1024
typedef __half bf16;   // limb type is fp16

__device__ __forceinline__ bf16 f2l(float v) { return __float2half_rn(v); }
__device__ __forceinline__ float l2f(bf16 v) { return __half2float(v); }

// ---------------- scratch (static device memory; no runtime alloc) ----------------
__device__ __align__(256) float g_A  [(size_t)B_*N_*N_];     // adjacency fp32
__device__ __align__(256) bf16  g_Lh [(size_t)B_*N_*N_];     // Laplacian hi (lo limb never needed)
__device__ __align__(256) bf16  g_Xh [(size_t)B_*N_*512];    // layer input split (ping)
__device__ __align__(256) bf16  g_Xl [(size_t)B_*N_*512];
__device__ __align__(256) bf16  g_Yh [(size_t)B_*N_*512];    // layer input split (pong)
__device__ __align__(256) bf16  g_Yl [(size_t)B_*N_*512];
__device__ __align__(256) bf16  g_Th [(size_t)B_*512*N_];    // transposed layer-input split
__device__ __align__(256) bf16  g_Tl [(size_t)B_*512*N_];
__device__ __align__(256) bf16  g_T2h[(size_t)B_*512*N_];    // transposed x1 split (epilogue-fused)
__device__ __align__(256) bf16  g_T2l[(size_t)B_*512*N_];
__device__ __align__(256) bf16  g_x1h[(size_t)B_*N_*512];
__device__ __align__(256) bf16  g_x2h[(size_t)B_*N_*512];
__device__ __align__(256) float g_H1 [(size_t)B_*N_*128];
__device__ __align__(256) float g_H2 [(size_t)B_*N_*512];
__device__ __align__(256) float g_H3 [(size_t)B_*N_*1024];
__device__ __align__(256) bf16  g_Wh [1024*1536];
__device__ __align__(256) bf16  g_Wl [1024*1536];
__device__ float g_sq [B_*N_];
__device__ float g_dis[B_*N_];
__device__ float g_pool[B_*1024];
__device__ float g_f1 [B_*512];
__device__ float g_f2 [B_*128];

// ---------------- PTX helpers ----------------
__device__ __forceinline__ uint32_t smem_u32(const void* p) {
    uint32_t a;
    asm("{ .reg .u64 t; cvta.to.shared.u64 t, %1; cvt.u32.u64 %0, t; }" : "=r"(a) : "l"(p));
    return a;
}
__device__ __forceinline__ void cpa16(uint32_t s, const void* g, int sz) {
    asm volatile("cp.async.cg.shared.global [%0], [%1], 16, %2;" :: "r"(s), "l"(g), "r"(sz));
}
#define CP_COMMIT() asm volatile("cp.async.commit_group;")
#define CP_WAIT0()  asm volatile("cp.async.wait_group 0;")
#define CP_WAIT1()  asm volatile("cp.async.wait_group 1;")

__device__ __forceinline__ void ldm4(uint32_t* r, uint32_t a) {
    asm volatile("ldmatrix.sync.aligned.m8n8.x4.shared.b16 {%0,%1,%2,%3}, [%4];"
        : "=r"(r[0]), "=r"(r[1]), "=r"(r[2]), "=r"(r[3]) : "r"(a));
}
__device__ __forceinline__ void mma_f16(float* d, const uint32_t* a, const uint32_t* b) {
    asm volatile("mma.sync.aligned.m16n8k16.row.col.f32.f16.f16.f32 "
        "{%0,%1,%2,%3},{%4,%5,%6,%7},{%8,%9},{%0,%1,%2,%3};"
        : "+f"(d[0]), "+f"(d[1]), "+f"(d[2]), "+f"(d[3])
        : "r"(a[0]), "r"(a[1]), "r"(a[2]), "r"(a[3]), "r"(b[0]), "r"(b[1]));
}

// smem tile: 128 rows x 32 fp16 cols, pitch 80B (64B data + 16B pad; 5r mod 8 permutation
// => conflict-free ldmatrix). K-chunk 32, double-buffered => 80KB => 2 CTAs/SM.
#define PITCH  80
#define TILEB  (128 * PITCH)     /* 10240 bytes per operand-limb tile */
#define STAGE  (4 * TILEB)       /* Ah | Al | Bh | Bl = 40960 */
#define SMEMSZ (2 * STAGE)       /* double buffered = 81920 */

// ---------------- split-fp16 HMMA GEMM ----------------
// C[M,Nv] = sum_seg A_seg[M,Kseg] * B[Nv,K]^T  (A row-major, B K-major [Nv,K])
// MODE 0: plain (2-prod)  MODE 1: __expf(2v-sq_i-sq_j), SYMMETRIC, 3-prod (exp amplifies error)
// MODE 2: 2v - aux (2-prod)   MODE 3: relu(v + bias) (2-prod)
// 2-prod = Ah*Bh + Ah*Bl (A-lo term ~2^-12 relative, dropped).
// Writes fp32 to Cf, split fp16 to Ch/Cl, transposed split to Cth/Ctl (each if non-null).
template<int MODE>
__global__ __launch_bounds__(256, 2) void gemm_mma(
    const bf16* A0h, const bf16* A0l, const bf16* A1h, const bf16* A1l,
    const bf16* A2h, const bf16* A2l,
    const bf16* Bh, const bf16* Bl,
    float* Cf, bf16* Ch, bf16* Cl, bf16* Cth, bf16* Ctl,
    int M, int Nv, int K, int Kseg,
    long long sA, long long sB, long long sC, long long sT,
    const float* sqv, const float* aux, const float* bias)
{
    if (MODE == 1 && blockIdx.x > blockIdx.y) return;   // symmetric: skip upper-tri blocks

    extern __shared__ char sm[];
    uint32_t sb = smem_u32(sm);
    int tid = threadIdx.x, lane = tid & 31, w = tid >> 5;
    int wm = w & 1, wn = w >> 1;          // 2 x 4 warp grid, warp tile 64x32
    int b = blockIdx.z;
    int iBase = blockIdx.y * 128, jBase = blockIdx.x * 128;

    const bf16* a0h = A0h + (size_t)b * sA;
    const bf16* a0l = A0l + (size_t)b * sA;
    const bf16* a1h = A1h + (size_t)b * sA;
    const bf16* a1l = A1l + (size_t)b * sA;
    const bf16* a2h = A2h + (size_t)b * sA;
    const bf16* a2l = A2l + (size_t)b * sA;
    const bf16* bhp = Bh + (size_t)b * sB;
    const bf16* blp = Bl + (size_t)b * sB;

    float acc[4][4][4];
    #pragma unroll
    for (int i = 0; i < 4; i++)
        #pragma unroll
        for (int j = 0; j < 4; j++)
            #pragma unroll
            for (int k = 0; k < 4; k++) acc[i][j][k] = 0.f;

    int nk = (K + 31) >> 5;
    bool vec = ((K & 31) == 0) && ((Kseg & 31) == 0);
    int Kseg2 = 2 * Kseg;

    // ---- hoisted per-thread load invariants (32-bit; all offsets < 2^31) ----
    int rA  = tid >> 2;                       // row within group
    int ccA = (tid & 3) * 8;                  // k-element offset of this 16B chunk
    int aRow0 = (iBase + rA) * Kseg;
    int aRow1 = (iBase + rA + 64) * Kseg;
    int gn0 = jBase + rA, gn1 = jBase + rA + 64;
    int ok0 = (gn0 < Nv) ? 16 : 0, ok1 = (gn1 < Nv) ? 16 : 0;
    int bRow0 = (ok0 ? gn0 : 0) * K;
    int bRow1 = (ok1 ? gn1 : 0) * K;
    uint32_t so0 = (uint32_t)(rA * PITCH + (tid & 3) * 16);
    uint32_t so1 = so0 + (uint32_t)(64 * PITCH);

    auto load_vec = [&](int stg, int kc0) {
        uint32_t base = sb + stg * STAGE;
        int kg = kc0 + ccA;
        int seg = (kg >= Kseg) + (kg >= Kseg2);       // comparison-based, no IDIV
        const bf16* ph = (seg == 0) ? a0h : ((seg == 1) ? a1h : a2h);
        int kloc = kg - seg * Kseg;
        // group 0 (rows 0..63)
        cpa16(base + so0,             ph + (aRow0 + kloc), 16);
        cpa16(base + so0 + 2 * TILEB, bhp + (bRow0 + kg), ok0);
        cpa16(base + so0 + 3 * TILEB, blp + (bRow0 + kg), ok0);
        // group 1 (rows 64..127)
        cpa16(base + so1,             ph + (aRow1 + kloc), 16);
        cpa16(base + so1 + 2 * TILEB, bhp + (bRow1 + kg), ok1);
        cpa16(base + so1 + 3 * TILEB, blp + (bRow1 + kg), ok1);
        if (MODE == 1) {               // A-lo limb only for the 3-product adjacency
            const bf16* pl = (seg == 0) ? a0l : ((seg == 1) ? a1l : a2l);
            cpa16(base + so0 + TILEB, pl + (aRow0 + kloc), 16);
            cpa16(base + so1 + TILEB, pl + (aRow1 + kloc), 16);
        }
    };

    auto compute = [&](int stg) {
        uint32_t base = sb + stg * STAGE;
        #pragma unroll
        for (int ks = 0; ks < 2; ks++) {
            int kk = ks * 16;
            uint32_t ah[4][4], al[4][4];
            #pragma unroll
            for (int i = 0; i < 4; i++) {
                int row = wm * 64 + i * 16 + (lane & 15);
                uint32_t ca = base + (uint32_t)(row * PITCH + ((lane >> 4) * 8 + kk) * 2);
                ldm4(ah[i], ca);
                if (MODE == 1) ldm4(al[i], ca + TILEB);
            }
            uint32_t bh[4][2], bl[4][2];
            #pragma unroll
            for (int jj = 0; jj < 2; jj++) {
                int rn = wn * 32 + jj * 16 + (lane & 7) + ((lane >> 4) & 1) * 8;
                uint32_t cb = base + 2 * TILEB +
                              (uint32_t)(rn * PITCH + (kk + ((lane >> 3) & 1) * 8) * 2);
                uint32_t t4[4];
                ldm4(t4, cb);
                bh[jj*2][0] = t4[0]; bh[jj*2][1] = t4[1];
                bh[jj*2+1][0] = t4[2]; bh[jj*2+1][1] = t4[3];
                ldm4(t4, cb + TILEB);
                bl[jj*2][0] = t4[0]; bl[jj*2][1] = t4[1];
                bl[jj*2+1][0] = t4[2]; bl[jj*2+1][1] = t4[3];
            }
            #pragma unroll
            for (int i = 0; i < 4; i++)
                #pragma unroll
                for (int j = 0; j < 4; j++) {
                    mma_f16(acc[i][j], ah[i], bh[j]);                   // hi*hi
                    mma_f16(acc[i][j], ah[i], bl[j]);                   // hi*lo
                    if (MODE == 1) mma_f16(acc[i][j], al[i], bh[j]);    // lo*hi (adjacency only)
                }
        }
    };

    if (vec) {
        // proven pipeline: load(i+1); commit; wait1; sync; compute(i); sync
        load_vec(0, 0); CP_COMMIT();
        for (int i = 0; i < nk; i++) {
            if (i + 1 < nk) { load_vec((i + 1) & 1, (i + 1) * 32); CP_COMMIT(); CP_WAIT1(); }
            else            { CP_WAIT0(); }
            __syncthreads();
            compute(i & 1);
            __syncthreads();
        }
    } else {
        // tiny-K path (layer 1 only: K=6 or K=18)
        for (int c = tid; c < STAGE / 16; c += 256) *(uint4*)(sm + (size_t)c * 16) = make_uint4(0,0,0,0);
        __syncthreads();
        for (int i = 0; i < nk; i++) {
            for (int idx = tid; idx < 128 * 32; idx += 256) {
                int r = idx >> 5, kc = idx & 31;
                int kg = i * 32 + kc;
                uint32_t so = (uint32_t)(r * PITCH + kc * 2);
                if (kg < K) {
                    int seg = (kg >= Kseg) + (kg >= Kseg2);
                    int kkk = kg - seg * Kseg;
                    const bf16* ph = (seg == 0) ? a0h : ((seg == 1) ? a1h : a2h);
                    *(bf16*)(sm + so) = ph[(size_t)(iBase + r) * Kseg + kkk];
                    if (MODE == 1) {
                        const bf16* pl = (seg == 0) ? a0l : ((seg == 1) ? a1l : a2l);
                        *(bf16*)(sm + so + TILEB) = pl[(size_t)(iBase + r) * Kseg + kkk];
                    }
                    int gn = jBase + r;
                    if (gn < Nv) {
                        *(bf16*)(sm + so + 2 * TILEB) = bhp[(size_t)gn * K + kg];
                        *(bf16*)(sm + so + 3 * TILEB) = blp[(size_t)gn * K + kg];
                    }
                }
            }
            __syncthreads();
            compute(0);
            __syncthreads();
            if (i + 1 < nk) {
                for (int c = tid; c < STAGE / 16; c += 256) *(uint4*)(sm + (size_t)c * 16) = make_uint4(0,0,0,0);
                __syncthreads();
            }
        }
    }

    // ---- epilogue (fused: fp32 / split fp16 / transposed split / symmetric mirror) ----
    int g = lane >> 2, t = lane & 3;
    float* Cb  = Cf  ? Cf  + (size_t)b * sC : nullptr;
    bf16* Chb  = Ch  ? Ch  + (size_t)b * sC : nullptr;
    bf16* Clb  = Cl  ? Cl  + (size_t)b * sC : nullptr;
    bf16* Cthb = Cth ? Cth + (size_t)b * sT : nullptr;
    bf16* Ctlb = Ctl ? Ctl + (size_t)b * sT : nullptr;
    bool mirror = (MODE == 1) && (blockIdx.x < blockIdx.y);
    #pragma unroll
    for (int i = 0; i < 4; i++) {
        #pragma unroll
        for (int rr = 0; rr < 2; rr++) {
            int row = iBase + wm * 64 + i * 16 + g + rr * 8;   // M is multiple of 128
            float sqi = (MODE == 1) ? sqv[b * N_ + row] : 0.f;
            #pragma unroll
            for (int j = 0; j < 4; j++) {
                int col = jBase + wn * 32 + j * 8 + 2 * t;
                #pragma unroll
                for (int cc = 0; cc < 2; cc++) {
                    int c2 = col + cc;
                    if (c2 < Nv) {
                        float v = acc[i][j][rr * 2 + cc];
                        if (MODE == 1)      v = __expf(2.f * v - sqi - sqv[b * N_ + c2]);
                        else if (MODE == 2) v = 2.f * v - aux[(size_t)b * sC + (size_t)row * Nv + c2];
                        else if (MODE == 3) v = fmaxf(v + bias[c2], 0.f);
                        size_t o = (size_t)row * Nv + c2;
                        if (Cb) {
                            Cb[o] = v;
                            if (mirror) Cb[(size_t)c2 * Nv + row] = v;   // symmetric mirror
                        }
                        if (Chb) {
                            bf16 h = f2l(v);
                            Chb[o] = h;
                            bf16 l = f2l(v - l2f(h));
                            if (Clb) Clb[o] = l;
                            if (Cthb) {                                   // fused transpose split
                                size_t ot = (size_t)c2 * N_ + row;
                                Cthb[ot] = h;
                                Ctlb[ot] = l;
                            }
                        }
                    }
                }
            }
        }
    }
}

// ---------------- conversion / elementwise kernels ----------------
__global__ void split_fp32(const float* __restrict__ X, bf16* __restrict__ H, bf16* __restrict__ L, size_t n) {
    size_t i = ((size_t)blockIdx.x * 256 + threadIdx.x) * 4;
    if (i >= n) return;
    float4 v = *(const float4*)(X + i);
    bf16 hv[4], lv[4];
    float vv[4] = {v.x, v.y, v.z, v.w};
    #pragma unroll
    for (int k = 0; k < 4; k++) {
        bf16 h = f2l(vv[k]);
        hv[k] = h;
        lv[k] = f2l(vv[k] - l2f(h));
    }
    *(uint2*)(H + i) = *(uint2*)hv;
    *(uint2*)(L + i) = *(uint2*)lv;
}

__global__ void transpose_split(const float* __restrict__ X, bf16* __restrict__ Th, bf16* __restrict__ Tl, int F) {
    __shared__ float tile[32][33];
    int b = blockIdx.z;
    int n0 = blockIdx.x * 32, f0 = blockIdx.y * 32;
    const float* Xb = X + (size_t)b * N_ * F;
    #pragma unroll
    for (int i = 0; i < 32; i += 8) {
        int nn = n0 + threadIdx.y + i, ff = f0 + threadIdx.x;
        if (ff < F) tile[threadIdx.y + i][threadIdx.x] = Xb[(size_t)nn * F + ff];
    }
    __syncthreads();
    bf16* Thb = Th + (size_t)b * F * N_;
    bf16* Tlb = Tl + (size_t)b * F * N_;
    #pragma unroll
    for (int i = 0; i < 32; i += 8) {
        int ff = f0 + threadIdx.y + i, nn = n0 + threadIdx.x;
        if (ff < F) {
            float v = tile[threadIdx.x][threadIdx.y + i];
            bf16 h = f2l(v);
            Thb[(size_t)ff * N_ + nn] = h;
            Tlb[(size_t)ff * N_ + nn] = f2l(v - l2f(h));
        }
    }
}

__global__ void wtrans(const float* __restrict__ W, bf16* __restrict__ Th, bf16* __restrict__ Tl, int Fi, int Fo) {
    int kg = blockIdx.x * 32 + threadIdx.x;
    int o  = blockIdx.y * 8 + threadIdx.y;
    int Kt = 3 * Fi;
    if (kg < Kt && o < Fo) {
        int seg = (kg >= Fi) + (kg >= 2 * Fi);
        int kc = kg - seg * Fi;
        float v = W[((size_t)seg * Fi + kc) * Fo + o];
        bf16 h = f2l(v);
        Th[(size_t)o * Kt + kg] = h;
        Tl[(size_t)o * Kt + kg] = f2l(v - l2f(h));
    }
}

__global__ void sqnorm(const float* __restrict__ X, float* __restrict__ sq, int F) {
    int row = blockIdx.x * 8 + threadIdx.y;
    const float* r = X + (size_t)row * F;
    float s = 0.f;
    for (int f = threadIdx.x; f < F; f += 32) { float v = r[f]; s += v * v; }
    #pragma unroll
    for (int o = 16; o; o >>= 1) s += __shfl_xor_sync(0xffffffffu, s, o);
    if (threadIdx.x == 0) sq[row] = s;
}

__global__ void rowdeg(const float* __restrict__ A, float* __restrict__ dis) {
    int row = blockIdx.x * 8 + threadIdx.y;
    const float* r = A + (size_t)row * N_;
    float s = 0.f;
    for (int m = threadIdx.x; m < N_; m += 32) s += r[m];
    #pragma unroll
    for (int o = 16; o; o >>= 1) s += __shfl_xor_sync(0xffffffffu, s, o);
    if (threadIdx.x == 0) dis[row] = rsqrtf(s);
}

// L = I - dis_i*A*dis_j, hi limb only (L-lo never consumed: L GEMMs are 2-product)
__global__ void makeL_split(const float* __restrict__ A, const float* __restrict__ dis,
                            bf16* __restrict__ Lh) {
    size_t idx = ((size_t)blockIdx.x * 256 + threadIdx.x) * 4;
    int j0 = (int)(idx & (N_ - 1));
    size_t t = idx >> 10;
    int i = (int)(t & (N_ - 1));
    int b = (int)(t >> 10);
    float di = dis[b * N_ + i];
    float4 a = *(const float4*)(A + idx);
    float av[4] = {a.x, a.y, a.z, a.w};
    bf16 hv[4];
    #pragma unroll
    for (int k = 0; k < 4; k++) {
        float v = -di * dis[b * N_ + j0 + k] * av[k];
        if (i == j0 + k) v += 1.f;
        hv[k] = f2l(v);
    }
    *(uint2*)(Lh + idx) = *(uint2*)hv;
}

__global__ void maxpool(const float* __restrict__ H, float* __restrict__ out) {
    int f = blockIdx.x * 256 + threadIdx.x;
    int b = blockIdx.y;
    const float* base = H + (size_t)b * N_ * 1024 + f;
    float m = -1e30f;
    for (int n = 0; n < N_; n++) m = fmaxf(m, base[(size_t)n * 1024]);
    out[b * 1024 + f] = m;
}

__global__ void fckernel(const float* __restrict__ in, const float* __restrict__ W,
                         const float* __restrict__ bias, float* __restrict__ out,
                         int K, int Nout, int dorelu) {
    __shared__ float s[1024];
    int b = blockIdx.x;
    for (int i = threadIdx.x; i < K; i += blockDim.x) s[i] = in[(size_t)b * K + i];
    __syncthreads();
    for (int j = threadIdx.x; j < Nout; j += blockDim.x) {
        float acc = bias[j];
        for (int i = 0; i < K; i++) acc = fmaf(s[i], W[(size_t)i * Nout + j], acc);
        if (dorelu) acc = fmaxf(acc, 0.f);
        out[(size_t)b * Nout + j] = acc;
    }
}

// ---------------- host orchestration ----------------
struct Ptrs {
    float *A, *sq, *dis;
    bf16 *Th, *Tl, *T2h, *T2l, *Lh, *x1h, *x2h, *Wh, *Wl;
};

// inH/inL: split of layer input P (already populated). outH/outL: split of H for next layer (may be null).
static void conv_layer(const float* P, bf16* inH, bf16* inL, int Fi, int Fo,
                       const float* W, const float* bias,
                       float* H, bf16* outH, bf16* outL, const Ptrs& p)
{
    dim3 tb32(32, 8);

    transpose_split<<<dim3(32, (Fi + 31) / 32, B_), tb32>>>(P, p.Th, p.Tl, Fi);
    sqnorm<<<B_ * N_ / 8, tb32>>>(P, p.sq, Fi);

    // adjacency: A = exp(2*X*X^T - sq_i - sq_j)  — symmetric, 3-product
    gemm_mma<1><<<dim3(8, 8, B_), 256, SMEMSZ>>>(
        inH, inL, inH, inL, inH, inL, inH, inL,
        p.A, nullptr, nullptr, nullptr, nullptr,
        N_, N_, Fi, Fi, (long long)N_ * Fi, (long long)N_ * Fi, (long long)N_ * N_, 0,
        p.sq, nullptr, nullptr);

    rowdeg<<<B_ * N_ / 8, tb32>>>(p.A, p.dis);
    makeL_split<<<(unsigned)((size_t)B_ * N_ * N_ / 1024), 256>>>(p.A, p.dis, p.Lh);

    // x1 = L @ x0 : 2-product (L hi only); split hi + fused transposed split (x2 gemm B)
    gemm_mma<0><<<dim3((Fi + 127) / 128, 8, B_), 256, SMEMSZ>>>(
        p.Lh, p.Lh, p.Lh, p.Lh, p.Lh, p.Lh, p.Th, p.Tl,
        nullptr, p.x1h, nullptr, p.T2h, p.T2l,
        N_, Fi, N_, N_, (long long)N_ * N_, (long long)Fi * N_, (long long)N_ * Fi, (long long)Fi * N_,
        nullptr, nullptr, nullptr);

    // x2 = 2 L @ x1 - x0 : 2-product; hi split only
    gemm_mma<2><<<dim3((Fi + 127) / 128, 8, B_), 256, SMEMSZ>>>(
        p.Lh, p.Lh, p.Lh, p.Lh, p.Lh, p.Lh, p.T2h, p.T2l,
        nullptr, p.x2h, nullptr, nullptr, nullptr,
        N_, Fi, N_, N_, (long long)N_ * N_, (long long)Fi * N_, (long long)N_ * Fi, 0,
        nullptr, P, nullptr);

    wtrans<<<dim3((3 * Fi + 31) / 32, (Fo + 7) / 8), tb32>>>(W, p.Wh, p.Wl, Fi, Fo);

    // H = relu(x0 W0 + x1 W1 + x2 W2 + b); 2-product; emits next layer's split
    gemm_mma<3><<<dim3((Fo + 127) / 128, B_ * N_ / 128, 1), 256, SMEMSZ>>>(
        inH, inH, p.x1h, p.x1h, p.x2h, p.x2h, p.Wh, p.Wl,
        H, outH, outL, nullptr, nullptr,
        B_ * N_, Fo, 3 * Fi, Fi, 0, 0, 0, 0,
        nullptr, nullptr, bias);
}

extern "C" void kernel_launch(void* const* d_in, const int* in_sizes, int n_in,
                              void* d_out, int out_size) {
    (void)in_sizes; (void)n_in; (void)out_size;
    const float* x     = (const float*)d_in[0];
    const float* W1    = (const float*)d_in[1];
    const float* b1    = (const float*)d_in[2];
    const float* W2    = (const float*)d_in[3];
    const float* b2    = (const float*)d_in[4];
    const float* W3    = (const float*)d_in[5];
    const float* b3    = (const float*)d_in[6];
    const float* fc1_w = (const float*)d_in[7];
    const float* fc1_b = (const float*)d_in[8];
    const float* fc2_w = (const float*)d_in[9];
    const float* fc2_b = (const float*)d_in[10];
    const float* fc3_w = (const float*)d_in[11];
    const float* fc3_b = (const float*)d_in[12];
    float* out = (float*)d_out;

    cudaFuncSetAttribute(gemm_mma<0>, cudaFuncAttributeMaxDynamicSharedMemorySize, SMEMSZ);
    cudaFuncSetAttribute(gemm_mma<1>, cudaFuncAttributeMaxDynamicSharedMemorySize, SMEMSZ);
    cudaFuncSetAttribute(gemm_mma<2>, cudaFuncAttributeMaxDynamicSharedMemorySize, SMEMSZ);
    cudaFuncSetAttribute(gemm_mma<3>, cudaFuncAttributeMaxDynamicSharedMemorySize, SMEMSZ);

    Ptrs p;
    bf16 *Xh, *Xl, *Yh, *Yl;
    float *H1, *H2, *H3, *pool, *f1, *f2;
    cudaGetSymbolAddress((void**)&p.A,   g_A);
    cudaGetSymbolAddress((void**)&p.sq,  g_sq);
    cudaGetSymbolAddress((void**)&p.dis, g_dis);
    cudaGetSymbolAddress((void**)&Xh,    g_Xh);
    cudaGetSymbolAddress((void**)&Xl,    g_Xl);
    cudaGetSymbolAddress((void**)&Yh,    g_Yh);
    cudaGetSymbolAddress((void**)&Yl,    g_Yl);
    cudaGetSymbolAddress((void**)&p.Th,  g_Th);
    cudaGetSymbolAddress((void**)&p.Tl,  g_Tl);
    cudaGetSymbolAddress((void**)&p.T2h, g_T2h);
    cudaGetSymbolAddress((void**)&p.T2l, g_T2l);
    cudaGetSymbolAddress((void**)&p.Lh,  g_Lh);
    cudaGetSymbolAddress((void**)&p.x1h, g_x1h);
    cudaGetSymbolAddress((void**)&p.x2h, g_x2h);
    cudaGetSymbolAddress((void**)&p.Wh,  g_Wh);
    cudaGetSymbolAddress((void**)&p.Wl,  g_Wl);
    cudaGetSymbolAddress((void**)&H1,    g_H1);
    cudaGetSymbolAddress((void**)&H2,    g_H2);
    cudaGetSymbolAddress((void**)&H3,    g_H3);
    cudaGetSymbolAddress((void**)&pool,  g_pool);
    cudaGetSymbolAddress((void**)&f1,    g_f1);
    cudaGetSymbolAddress((void**)&f2,    g_f2);

    // layer 1: split the raw input, H1 split -> Y
    split_fp32<<<(unsigned)(((size_t)B_ * N_ * 6 + 1023) / 1024), 256>>>(x, Xh, Xl, (size_t)B_ * N_ * 6);
    conv_layer(x,  Xh, Xl, 6,   128,  W1, b1, H1, Yh, Yl, p);
    // layer 2: input split = Y, H2 split -> X (ping-pong)
    conv_layer(H1, Yh, Yl, 128, 512,  W2, b2, H2, Xh, Xl, p);
    // layer 3: input split = X, no H split needed
    conv_layer(H2, Xh, Xl, 512, 1024, W3, b3, H3, nullptr, nullptr, p);

    maxpool<<<dim3(4, B_), 256>>>(H3, pool);
    fckernel<<<B_, 256>>>(pool, fc1_w, fc1_b, f1, 1024, 512, 1);
    fckernel<<<B_, 256>>>(f1,   fc2_w, fc2_b, f2, 512, 128, 1);
    fckernel<<<B_, 256>>>(f2,   fc3_w, fc3_b, out, 128, 40, 0);
}

// round 16
// speedup vs baseline: 2.2264x; 1.0966x over previous
#include <cuda_runtime.h>
#include <cuda_fp16.h>
#include <math.h>
#include <stdint.h>

#define B_ 32
#define N_ 1024
typedef __half bf16;   // limb type is fp16

__device__ __forceinline__ bf16 f2l(float v) { return __float2half_rn(v); }
__device__ __forceinline__ float l2f(bf16 v) { return __half2float(v); }

// ---------------- scratch (static device memory; no runtime alloc) ----------------
__device__ __align__(256) float g_A  [(size_t)B_*N_*N_];     // adjacency fp32
__device__ __align__(256) bf16  g_Lh [(size_t)B_*N_*N_];     // Laplacian hi (lo limb never needed)
__device__ __align__(256) bf16  g_Xh [(size_t)B_*N_*512];    // layer input split (ping)
__device__ __align__(256) bf16  g_Xl [(size_t)B_*N_*512];
__device__ __align__(256) bf16  g_Yh [(size_t)B_*N_*512];    // layer input split (pong)
__device__ __align__(256) bf16  g_Yl [(size_t)B_*N_*512];
__device__ __align__(256) bf16  g_Th [(size_t)B_*512*N_];    // transposed layer-input split
__device__ __align__(256) bf16  g_Tl [(size_t)B_*512*N_];
__device__ __align__(256) bf16  g_T2h[(size_t)B_*512*N_];    // transposed x1 split (epilogue-fused)
__device__ __align__(256) bf16  g_T2l[(size_t)B_*512*N_];
__device__ __align__(256) bf16  g_x1h[(size_t)B_*N_*512];
__device__ __align__(256) bf16  g_x2h[(size_t)B_*N_*512];
__device__ __align__(256) float g_H1 [(size_t)B_*N_*128];
__device__ __align__(256) float g_H2 [(size_t)B_*N_*512];
__device__ __align__(256) float g_H3 [(size_t)B_*N_*1024];
__device__ __align__(256) bf16  g_Wh [1024*1536];
__device__ float g_sq [B_*N_];
__device__ float g_dis[B_*N_];
__device__ float g_pool[B_*1024];
__device__ float g_f1 [B_*512];
__device__ float g_f2 [B_*128];

// ---------------- PTX helpers ----------------
__device__ __forceinline__ uint32_t smem_u32(const void* p) {
    uint32_t a;
    asm("{ .reg .u64 t; cvta.to.shared.u64 t, %1; cvt.u32.u64 %0, t; }" : "=r"(a) : "l"(p));
    return a;
}
__device__ __forceinline__ void cpa16(uint32_t s, const void* g, int sz) {
    asm volatile("cp.async.cg.shared.global [%0], [%1], 16, %2;" :: "r"(s), "l"(g), "r"(sz));
}
#define CP_COMMIT() asm volatile("cp.async.commit_group;")
#define CP_WAIT0()  asm volatile("cp.async.wait_group 0;")
#define CP_WAIT1()  asm volatile("cp.async.wait_group 1;")

__device__ __forceinline__ void ldm4(uint32_t* r, uint32_t a) {
    asm volatile("ldmatrix.sync.aligned.m8n8.x4.shared.b16 {%0,%1,%2,%3}, [%4];"
        : "=r"(r[0]), "=r"(r[1]), "=r"(r[2]), "=r"(r[3]) : "r"(a));
}
__device__ __forceinline__ void mma_f16(float* d, const uint32_t* a, const uint32_t* b) {
    asm volatile("mma.sync.aligned.m16n8k16.row.col.f32.f16.f16.f32 "
        "{%0,%1,%2,%3},{%4,%5,%6,%7},{%8,%9},{%0,%1,%2,%3};"
        : "+f"(d[0]), "+f"(d[1]), "+f"(d[2]), "+f"(d[3])
        : "r"(a[0]), "r"(a[1]), "r"(a[2]), "r"(a[3]), "r"(b[0]), "r"(b[1]));
}

// smem tile: 128 rows x 32 fp16 cols, pitch 80B (64B data + 16B pad; 5r mod 8 permutation
// => conflict-free ldmatrix). K-chunk 32, double-buffered => 80KB => 2 CTAs/SM.
#define PITCH  80
#define TILEB  (128 * PITCH)     /* 10240 bytes per operand-limb tile */
#define STAGE  (4 * TILEB)       /* Ah | Al | Bh | Bl = 40960 */
#define SMEMSZ (2 * STAGE)       /* double buffered = 81920 */

// ---------------- split-fp16 HMMA GEMM ----------------
// C[M,Nv] = sum_seg A_seg[M,Kseg] * B[Nv,K]^T  (A row-major, B K-major [Nv,K])
// MODE 0: plain (2-prod Ah*Bh+Ah*Bl)
// MODE 1: __expf(2v-sq_i-sq_j), SYMMETRIC, 3-prod (exp amplifies error)
// MODE 2: 2v - aux (2-prod)
// MODE 3: relu(v + bias), 1-PRODUCT (pure fp16 Ah*Bh; x-lo and W-lo both ~2^-12)
// Writes fp32 to Cf, split fp16 to Ch/Cl, transposed split to Cth/Ctl (each if non-null).
template<int MODE>
__global__ __launch_bounds__(256, 2) void gemm_mma(
    const bf16* A0h, const bf16* A0l, const bf16* A1h, const bf16* A1l,
    const bf16* A2h, const bf16* A2l,
    const bf16* Bh, const bf16* Bl,
    float* Cf, bf16* Ch, bf16* Cl, bf16* Cth, bf16* Ctl,
    int M, int Nv, int K, int Kseg,
    long long sA, long long sB, long long sC, long long sT,
    const float* sqv, const float* aux, const float* bias)
{
    if (MODE == 1 && blockIdx.x > blockIdx.y) return;   // symmetric: skip upper-tri blocks

    extern __shared__ char sm[];
    uint32_t sb = smem_u32(sm);
    int tid = threadIdx.x, lane = tid & 31, w = tid >> 5;
    int wm = w & 1, wn = w >> 1;          // 2 x 4 warp grid, warp tile 64x32
    int b = blockIdx.z;
    int iBase = blockIdx.y * 128, jBase = blockIdx.x * 128;

    const bf16* a0h = A0h + (size_t)b * sA;
    const bf16* a0l = A0l + (size_t)b * sA;
    const bf16* a1h = A1h + (size_t)b * sA;
    const bf16* a1l = A1l + (size_t)b * sA;
    const bf16* a2h = A2h + (size_t)b * sA;
    const bf16* a2l = A2l + (size_t)b * sA;
    const bf16* bhp = Bh + (size_t)b * sB;
    const bf16* blp = Bl + (size_t)b * sB;

    float acc[4][4][4];
    #pragma unroll
    for (int i = 0; i < 4; i++)
        #pragma unroll
        for (int j = 0; j < 4; j++)
            #pragma unroll
            for (int k = 0; k < 4; k++) acc[i][j][k] = 0.f;

    int nk = (K + 31) >> 5;
    bool vec = ((K & 31) == 0) && ((Kseg & 31) == 0);
    int Kseg2 = 2 * Kseg;

    // ---- hoisted per-thread load invariants (32-bit; all offsets < 2^31) ----
    int rA  = tid >> 2;                       // row within group
    int ccA = (tid & 3) * 8;                  // k-element offset of this 16B chunk
    int aRow0 = (iBase + rA) * Kseg;
    int aRow1 = (iBase + rA + 64) * Kseg;
    int gn0 = jBase + rA, gn1 = jBase + rA + 64;
    int ok0 = (gn0 < Nv) ? 16 : 0, ok1 = (gn1 < Nv) ? 16 : 0;
    int bRow0 = (ok0 ? gn0 : 0) * K;
    int bRow1 = (ok1 ? gn1 : 0) * K;
    uint32_t so0 = (uint32_t)(rA * PITCH + (tid & 3) * 16);
    uint32_t so1 = so0 + (uint32_t)(64 * PITCH);

    auto load_vec = [&](int stg, int kc0) {
        uint32_t base = sb + stg * STAGE;
        int kg = kc0 + ccA;
        int seg = (kg >= Kseg) + (kg >= Kseg2);       // comparison-based, no IDIV
        const bf16* ph = (seg == 0) ? a0h : ((seg == 1) ? a1h : a2h);
        int kloc = kg - seg * Kseg;
        // group 0 (rows 0..63)
        cpa16(base + so0,             ph + (aRow0 + kloc), 16);
        cpa16(base + so0 + 2 * TILEB, bhp + (bRow0 + kg), ok0);
        // group 1 (rows 64..127)
        cpa16(base + so1,             ph + (aRow1 + kloc), 16);
        cpa16(base + so1 + 2 * TILEB, bhp + (bRow1 + kg), ok1);
        if (MODE != 3) {               // B-lo limb: not needed for 1-product feature gemm
            cpa16(base + so0 + 3 * TILEB, blp + (bRow0 + kg), ok0);
            cpa16(base + so1 + 3 * TILEB, blp + (bRow1 + kg), ok1);
        }
        if (MODE == 1) {               // A-lo limb only for the 3-product adjacency
            const bf16* pl = (seg == 0) ? a0l : ((seg == 1) ? a1l : a2l);
            cpa16(base + so0 + TILEB, pl + (aRow0 + kloc), 16);
            cpa16(base + so1 + TILEB, pl + (aRow1 + kloc), 16);
        }
    };

    auto compute = [&](int stg) {
        uint32_t base = sb + stg * STAGE;
        #pragma unroll
        for (int ks = 0; ks < 2; ks++) {
            int kk = ks * 16;
            uint32_t ah[4][4], al[4][4];
            #pragma unroll
            for (int i = 0; i < 4; i++) {
                int row = wm * 64 + i * 16 + (lane & 15);
                uint32_t ca = base + (uint32_t)(row * PITCH + ((lane >> 4) * 8 + kk) * 2);
                ldm4(ah[i], ca);
                if (MODE == 1) ldm4(al[i], ca + TILEB);
            }
            uint32_t bh[4][2], bl[4][2];
            #pragma unroll
            for (int jj = 0; jj < 2; jj++) {
                int rn = wn * 32 + jj * 16 + (lane & 7) + ((lane >> 4) & 1) * 8;
                uint32_t cb = base + 2 * TILEB +
                              (uint32_t)(rn * PITCH + (kk + ((lane >> 3) & 1) * 8) * 2);
                uint32_t t4[4];
                ldm4(t4, cb);
                bh[jj*2][0] = t4[0]; bh[jj*2][1] = t4[1];
                bh[jj*2+1][0] = t4[2]; bh[jj*2+1][1] = t4[3];
                if (MODE != 3) {
                    ldm4(t4, cb + TILEB);
                    bl[jj*2][0] = t4[0]; bl[jj*2][1] = t4[1];
                    bl[jj*2+1][0] = t4[2]; bl[jj*2+1][1] = t4[3];
                }
            }
            #pragma unroll
            for (int i = 0; i < 4; i++)
                #pragma unroll
                for (int j = 0; j < 4; j++) {
                    mma_f16(acc[i][j], ah[i], bh[j]);                   // hi*hi
                    if (MODE != 3) mma_f16(acc[i][j], ah[i], bl[j]);    // hi*lo
                    if (MODE == 1) mma_f16(acc[i][j], al[i], bh[j]);    // lo*hi (adjacency only)
                }
        }
    };

    if (vec) {
        // proven pipeline: load(i+1); commit; wait1; sync; compute(i); sync
        load_vec(0, 0); CP_COMMIT();
        for (int i = 0; i < nk; i++) {
            if (i + 1 < nk) { load_vec((i + 1) & 1, (i + 1) * 32); CP_COMMIT(); CP_WAIT1(); }
            else            { CP_WAIT0(); }
            __syncthreads();
            compute(i & 1);
            __syncthreads();
        }
    } else {
        // tiny-K path (layer 1 only: K=6 or K=18)
        for (int c = tid; c < STAGE / 16; c += 256) *(uint4*)(sm + (size_t)c * 16) = make_uint4(0,0,0,0);
        __syncthreads();
        for (int i = 0; i < nk; i++) {
            for (int idx = tid; idx < 128 * 32; idx += 256) {
                int r = idx >> 5, kc = idx & 31;
                int kg = i * 32 + kc;
                uint32_t so = (uint32_t)(r * PITCH + kc * 2);
                if (kg < K) {
                    int seg = (kg >= Kseg) + (kg >= Kseg2);
                    int kkk = kg - seg * Kseg;
                    const bf16* ph = (seg == 0) ? a0h : ((seg == 1) ? a1h : a2h);
                    *(bf16*)(sm + so) = ph[(size_t)(iBase + r) * Kseg + kkk];
                    if (MODE == 1) {
                        const bf16* pl = (seg == 0) ? a0l : ((seg == 1) ? a1l : a2l);
                        *(bf16*)(sm + so + TILEB) = pl[(size_t)(iBase + r) * Kseg + kkk];
                    }
                    int gn = jBase + r;
                    if (gn < Nv) {
                        *(bf16*)(sm + so + 2 * TILEB) = bhp[(size_t)gn * K + kg];
                        if (MODE != 3)
                            *(bf16*)(sm + so + 3 * TILEB) = blp[(size_t)gn * K + kg];
                    }
                }
            }
            __syncthreads();
            compute(0);
            __syncthreads();
            if (i + 1 < nk) {
                for (int c = tid; c < STAGE / 16; c += 256) *(uint4*)(sm + (size_t)c * 16) = make_uint4(0,0,0,0);
                __syncthreads();
            }
        }
    }

    // ---- epilogue (fused: fp32 / split fp16 / transposed split / symmetric mirror) ----
    int g = lane >> 2, t = lane & 3;
    float* Cb  = Cf  ? Cf  + (size_t)b * sC : nullptr;
    bf16* Chb  = Ch  ? Ch  + (size_t)b * sC : nullptr;
    bf16* Clb  = Cl  ? Cl  + (size_t)b * sC : nullptr;
    bf16* Cthb = Cth ? Cth + (size_t)b * sT : nullptr;
    bf16* Ctlb = Ctl ? Ctl + (size_t)b * sT : nullptr;
    bool mirror = (MODE == 1) && (blockIdx.x < blockIdx.y);
    #pragma unroll
    for (int i = 0; i < 4; i++) {
        #pragma unroll
        for (int rr = 0; rr < 2; rr++) {
            int row = iBase + wm * 64 + i * 16 + g + rr * 8;   // M is multiple of 128
            float sqi = (MODE == 1) ? sqv[b * N_ + row] : 0.f;
            #pragma unroll
            for (int j = 0; j < 4; j++) {
                int col = jBase + wn * 32 + j * 8 + 2 * t;
                #pragma unroll
                for (int cc = 0; cc < 2; cc++) {
                    int c2 = col + cc;
                    if (c2 < Nv) {
                        float v = acc[i][j][rr * 2 + cc];
                        if (MODE == 1)      v = __expf(2.f * v - sqi - sqv[b * N_ + c2]);
                        else if (MODE == 2) v = 2.f * v - aux[(size_t)b * sC + (size_t)row * Nv + c2];
                        else if (MODE == 3) v = fmaxf(v + bias[c2], 0.f);
                        size_t o = (size_t)row * Nv + c2;
                        if (Cb) {
                            Cb[o] = v;
                            if (mirror) Cb[(size_t)c2 * Nv + row] = v;   // symmetric mirror
                        }
                        if (Chb) {
                            bf16 h = f2l(v);
                            Chb[o] = h;
                            bf16 l = f2l(v - l2f(h));
                            if (Clb) Clb[o] = l;
                            if (Cthb) {                                   // fused transpose split
                                size_t ot = (size_t)c2 * N_ + row;
                                Cthb[ot] = h;
                                Ctlb[ot] = l;
                            }
                        }
                    }
                }
            }
        }
    }
}

// ---------------- conversion / elementwise kernels ----------------
__global__ void split_fp32(const float* __restrict__ X, bf16* __restrict__ H, bf16* __restrict__ L, size_t n) {
    size_t i = ((size_t)blockIdx.x * 256 + threadIdx.x) * 4;
    if (i >= n) return;
    float4 v = *(const float4*)(X + i);
    bf16 hv[4], lv[4];
    float vv[4] = {v.x, v.y, v.z, v.w};
    #pragma unroll
    for (int k = 0; k < 4; k++) {
        bf16 h = f2l(vv[k]);
        hv[k] = h;
        lv[k] = f2l(vv[k] - l2f(h));
    }
    *(uint2*)(H + i) = *(uint2*)hv;
    *(uint2*)(L + i) = *(uint2*)lv;
}

__global__ void transpose_split(const float* __restrict__ X, bf16* __restrict__ Th, bf16* __restrict__ Tl, int F) {
    __shared__ float tile[32][33];
    int b = blockIdx.z;
    int n0 = blockIdx.x * 32, f0 = blockIdx.y * 32;
    const float* Xb = X + (size_t)b * N_ * F;
    #pragma unroll
    for (int i = 0; i < 32; i += 8) {
        int nn = n0 + threadIdx.y + i, ff = f0 + threadIdx.x;
        if (ff < F) tile[threadIdx.y + i][threadIdx.x] = Xb[(size_t)nn * F + ff];
    }
    __syncthreads();
    bf16* Thb = Th + (size_t)b * F * N_;
    bf16* Tlb = Tl + (size_t)b * F * N_;
    #pragma unroll
    for (int i = 0; i < 32; i += 8) {
        int ff = f0 + threadIdx.y + i, nn = n0 + threadIdx.x;
        if (ff < F) {
            float v = tile[threadIdx.x][threadIdx.y + i];
            bf16 h = f2l(v);
            Thb[(size_t)ff * N_ + nn] = h;
            Tlb[(size_t)ff * N_ + nn] = f2l(v - l2f(h));
        }
    }
}

// weights: hi limb only (feature gemm is single-product)
__global__ void wtrans(const float* __restrict__ W, bf16* __restrict__ Th, int Fi, int Fo) {
    int kg = blockIdx.x * 32 + threadIdx.x;
    int o  = blockIdx.y * 8 + threadIdx.y;
    int Kt = 3 * Fi;
    if (kg < Kt && o < Fo) {
        int seg = (kg >= Fi) + (kg >= 2 * Fi);
        int kc = kg - seg * Fi;
        float v = W[((size_t)seg * Fi + kc) * Fo + o];
        Th[(size_t)o * Kt + kg] = f2l(v);
    }
}

__global__ void sqnorm(const float* __restrict__ X, float* __restrict__ sq, int F) {
    int row = blockIdx.x * 8 + threadIdx.y;
    const float* r = X + (size_t)row * F;
    float s = 0.f;
    for (int f = threadIdx.x; f < F; f += 32) { float v = r[f]; s += v * v; }
    #pragma unroll
    for (int o = 16; o; o >>= 1) s += __shfl_xor_sync(0xffffffffu, s, o);
    if (threadIdx.x == 0) sq[row] = s;
}

__global__ void rowdeg(const float* __restrict__ A, float* __restrict__ dis) {
    int row = blockIdx.x * 8 + threadIdx.y;
    const float* r = A + (size_t)row * N_;
    float s = 0.f;
    for (int m = threadIdx.x; m < N_; m += 32) s += r[m];
    #pragma unroll
    for (int o = 16; o; o >>= 1) s += __shfl_xor_sync(0xffffffffu, s, o);
    if (threadIdx.x == 0) dis[row] = rsqrtf(s);
}

// L = I - dis_i*A*dis_j, hi limb only (L-lo never consumed)
__global__ void makeL_split(const float* __restrict__ A, const float* __restrict__ dis,
                            bf16* __restrict__ Lh) {
    size_t idx = ((size_t)blockIdx.x * 256 + threadIdx.x) * 4;
    int j0 = (int)(idx & (N_ - 1));
    size_t t = idx >> 10;
    int i = (int)(t & (N_ - 1));
    int b = (int)(t >> 10);
    float di = dis[b * N_ + i];
    float4 a = *(const float4*)(A + idx);
    float av[4] = {a.x, a.y, a.z, a.w};
    bf16 hv[4];
    #pragma unroll
    for (int k = 0; k < 4; k++) {
        float v = -di * dis[b * N_ + j0 + k] * av[k];
        if (i == j0 + k) v += 1.f;
        hv[k] = f2l(v);
    }
    *(uint2*)(Lh + idx) = *(uint2*)hv;
}

__global__ void maxpool(const float* __restrict__ H, float* __restrict__ out) {
    int f = blockIdx.x * 256 + threadIdx.x;
    int b = blockIdx.y;
    const float* base = H + (size_t)b * N_ * 1024 + f;
    float m = -1e30f;
    for (int n = 0; n < N_; n++) m = fmaxf(m, base[(size_t)n * 1024]);
    out[b * 1024 + f] = m;
}

__global__ void fckernel(const float* __restrict__ in, const float* __restrict__ W,
                         const float* __restrict__ bias, float* __restrict__ out,
                         int K, int Nout, int dorelu) {
    __shared__ float s[1024];
    int b = blockIdx.x;
    for (int i = threadIdx.x; i < K; i += blockDim.x) s[i] = in[(size_t)b * K + i];
    __syncthreads();
    for (int j = threadIdx.x; j < Nout; j += blockDim.x) {
        float acc = bias[j];
        for (int i = 0; i < K; i++) acc = fmaf(s[i], W[(size_t)i * Nout + j], acc);
        if (dorelu) acc = fmaxf(acc, 0.f);
        out[(size_t)b * Nout + j] = acc;
    }
}

// ---------------- host orchestration ----------------
struct Ptrs {
    float *A, *sq, *dis;
    bf16 *Th, *Tl, *T2h, *T2l, *Lh, *x1h, *x2h, *Wh;
};

// inH/inL: split of layer input P (already populated). outH/outL: split of H for next layer (may be null).
static void conv_layer(const float* P, bf16* inH, bf16* inL, int Fi, int Fo,
                       const float* W, const float* bias,
                       float* H, bf16* outH, bf16* outL, const Ptrs& p)
{
    dim3 tb32(32, 8);

    transpose_split<<<dim3(32, (Fi + 31) / 32, B_), tb32>>>(P, p.Th, p.Tl, Fi);
    sqnorm<<<B_ * N_ / 8, tb32>>>(P, p.sq, Fi);

    // adjacency: A = exp(2*X*X^T - sq_i - sq_j)  — symmetric, 3-product
    gemm_mma<1><<<dim3(8, 8, B_), 256, SMEMSZ>>>(
        inH, inL, inH, inL, inH, inL, inH, inL,
        p.A, nullptr, nullptr, nullptr, nullptr,
        N_, N_, Fi, Fi, (long long)N_ * Fi, (long long)N_ * Fi, (long long)N_ * N_, 0,
        p.sq, nullptr, nullptr);

    rowdeg<<<B_ * N_ / 8, tb32>>>(p.A, p.dis);
    makeL_split<<<(unsigned)((size_t)B_ * N_ * N_ / 1024), 256>>>(p.A, p.dis, p.Lh);

    // x1 = L @ x0 : 2-product (L hi only); split hi + fused transposed split (x2 gemm B)
    gemm_mma<0><<<dim3((Fi + 127) / 128, 8, B_), 256, SMEMSZ>>>(
        p.Lh, p.Lh, p.Lh, p.Lh, p.Lh, p.Lh, p.Th, p.Tl,
        nullptr, p.x1h, nullptr, p.T2h, p.T2l,
        N_, Fi, N_, N_, (long long)N_ * N_, (long long)Fi * N_, (long long)N_ * Fi, (long long)Fi * N_,
        nullptr, nullptr, nullptr);

    // x2 = 2 L @ x1 - x0 : 2-product; hi split only
    gemm_mma<2><<<dim3((Fi + 127) / 128, 8, B_), 256, SMEMSZ>>>(
        p.Lh, p.Lh, p.Lh, p.Lh, p.Lh, p.Lh, p.T2h, p.T2l,
        nullptr, p.x2h, nullptr, nullptr, nullptr,
        N_, Fi, N_, N_, (long long)N_ * N_, (long long)Fi * N_, (long long)N_ * Fi, 0,
        nullptr, P, nullptr);

    wtrans<<<dim3((3 * Fi + 31) / 32, (Fo + 7) / 8), tb32>>>(W, p.Wh, Fi, Fo);

    // H = relu(x0 W0 + x1 W1 + x2 W2 + b); 1-product (pure fp16); emits next layer's split
    gemm_mma<3><<<dim3((Fo + 127) / 128, B_ * N_ / 128, 1), 256, SMEMSZ>>>(
        inH, inH, p.x1h, p.x1h, p.x2h, p.x2h, p.Wh, p.Wh,
        H, outH, outL, nullptr, nullptr,
        B_ * N_, Fo, 3 * Fi, Fi, 0, 0, 0, 0,
        nullptr, nullptr, bias);
}

extern "C" void kernel_launch(void* const* d_in, const int* in_sizes, int n_in,
                              void* d_out, int out_size) {
    (void)in_sizes; (void)n_in; (void)out_size;
    const float* x     = (const float*)d_in[0];
    const float* W1    = (const float*)d_in[1];
    const float* b1    = (const float*)d_in[2];
    const float* W2    = (const float*)d_in[3];
    const float* b2    = (const float*)d_in[4];
    const float* W3    = (const float*)d_in[5];
    const float* b3    = (const float*)d_in[6];
    const float* fc1_w = (const float*)d_in[7];
    const float* fc1_b = (const float*)d_in[8];
    const float* fc2_w = (const float*)d_in[9];
    const float* fc2_b = (const float*)d_in[10];
    const float* fc3_w = (const float*)d_in[11];
    const float* fc3_b = (const float*)d_in[12];
    float* out = (float*)d_out;

    cudaFuncSetAttribute(gemm_mma<0>, cudaFuncAttributeMaxDynamicSharedMemorySize, SMEMSZ);
    cudaFuncSetAttribute(gemm_mma<1>, cudaFuncAttributeMaxDynamicSharedMemorySize, SMEMSZ);
    cudaFuncSetAttribute(gemm_mma<2>, cudaFuncAttributeMaxDynamicSharedMemorySize, SMEMSZ);
    cudaFuncSetAttribute(gemm_mma<3>, cudaFuncAttributeMaxDynamicSharedMemorySize, SMEMSZ);

    Ptrs p;
    bf16 *Xh, *Xl, *Yh, *Yl;
    float *H1, *H2, *H3, *pool, *f1, *f2;
    cudaGetSymbolAddress((void**)&p.A,   g_A);
    cudaGetSymbolAddress((void**)&p.sq,  g_sq);
    cudaGetSymbolAddress((void**)&p.dis, g_dis);
    cudaGetSymbolAddress((void**)&Xh,    g_Xh);
    cudaGetSymbolAddress((void**)&Xl,    g_Xl);
    cudaGetSymbolAddress((void**)&Yh,    g_Yh);
    cudaGetSymbolAddress((void**)&Yl,    g_Yl);
    cudaGetSymbolAddress((void**)&p.Th,  g_Th);
    cudaGetSymbolAddress((void**)&p.Tl,  g_Tl);
    cudaGetSymbolAddress((void**)&p.T2h, g_T2h);
    cudaGetSymbolAddress((void**)&p.T2l, g_T2l);
    cudaGetSymbolAddress((void**)&p.Lh,  g_Lh);
    cudaGetSymbolAddress((void**)&p.x1h, g_x1h);
    cudaGetSymbolAddress((void**)&p.x2h, g_x2h);
    cudaGetSymbolAddress((void**)&p.Wh,  g_Wh);
    cudaGetSymbolAddress((void**)&H1,    g_H1);
    cudaGetSymbolAddress((void**)&H2,    g_H2);
    cudaGetSymbolAddress((void**)&H3,    g_H3);
    cudaGetSymbolAddress((void**)&pool,  g_pool);
    cudaGetSymbolAddress((void**)&f1,    g_f1);
    cudaGetSymbolAddress((void**)&f2,    g_f2);

    // layer 1: split the raw input, H1 split -> Y
    split_fp32<<<(unsigned)(((size_t)B_ * N_ * 6 + 1023) / 1024), 256>>>(x, Xh, Xl, (size_t)B_ * N_ * 6);
    conv_layer(x,  Xh, Xl, 6,   128,  W1, b1, H1, Yh, Yl, p);
    // layer 2: input split = Y, H2 split -> X (ping-pong)
    conv_layer(H1, Yh, Yl, 128, 512,  W2, b2, H2, Xh, Xl, p);
    // layer 3: input split = X, no H split needed
    conv_layer(H2, Xh, Xl, 512, 1024, W3, b3, H3, nullptr, nullptr, p);

    maxpool<<<dim3(4, B_), 256>>>(H3, pool);
    fckernel<<<B_, 256>>>(pool, fc1_w, fc1_b, f1, 1024, 512, 1);
    fckernel<<<B_, 256>>>(f1,   fc2_w, fc2_b, f2, 512, 128, 1);
    fckernel<<<B_, 256>>>(f2,   fc3_w, fc3_b, out, 128, 40, 0);
}

// round 17
// speedup vs baseline: 2.5181x; 1.1310x over previous
#include <cuda_runtime.h>
#include <cuda_fp16.h>
#include <math.h>
#include <stdint.h>

#define B_ 32
#define N_ 1024
typedef __half bf16;   // limb type is fp16

__device__ __forceinline__ bf16 f2l(float v) { return __float2half_rn(v); }
__device__ __forceinline__ float l2f(bf16 v) { return __half2float(v); }

// ---------------- scratch (static device memory; no runtime alloc) ----------------
__device__ __align__(256) bf16  g_A  [(size_t)B_*N_*N_];     // adjacency fp16 (hi only)
__device__ __align__(256) bf16  g_Lh [(size_t)B_*N_*N_];     // Laplacian hi
__device__ __align__(256) bf16  g_Xh [(size_t)B_*N_*512];    // layer input split (ping)
__device__ __align__(256) bf16  g_Xl [(size_t)B_*N_*512];
__device__ __align__(256) bf16  g_Yh [(size_t)B_*N_*512];    // layer input split (pong)
__device__ __align__(256) bf16  g_Yl [(size_t)B_*N_*512];
__device__ __align__(256) bf16  g_Th [(size_t)B_*512*N_];    // transposed layer-input (hi)
__device__ __align__(256) bf16  g_T2h[(size_t)B_*512*N_];    // transposed x1 (hi, epilogue-fused)
__device__ __align__(256) bf16  g_x1h[(size_t)B_*N_*512];
__device__ __align__(256) bf16  g_x2h[(size_t)B_*N_*512];
__device__ __align__(256) float g_H1 [(size_t)B_*N_*128];
__device__ __align__(256) float g_H2 [(size_t)B_*N_*512];
__device__ __align__(256) float g_H3 [(size_t)B_*N_*1024];
__device__ __align__(256) bf16  g_Wh [1024*1536];
__device__ float g_sq [B_*N_];
__device__ float g_dis[B_*N_];
__device__ float g_pool[B_*1024];
__device__ float g_f1 [B_*512];
__device__ float g_f2 [B_*128];

// ---------------- PTX helpers ----------------
__device__ __forceinline__ uint32_t smem_u32(const void* p) {
    uint32_t a;
    asm("{ .reg .u64 t; cvta.to.shared.u64 t, %1; cvt.u32.u64 %0, t; }" : "=r"(a) : "l"(p));
    return a;
}
__device__ __forceinline__ void cpa16(uint32_t s, const void* g, int sz) {
    asm volatile("cp.async.cg.shared.global [%0], [%1], 16, %2;" :: "r"(s), "l"(g), "r"(sz));
}
#define CP_COMMIT() asm volatile("cp.async.commit_group;")
#define CP_WAIT0()  asm volatile("cp.async.wait_group 0;")
#define CP_WAIT1()  asm volatile("cp.async.wait_group 1;")

__device__ __forceinline__ void ldm4(uint32_t* r, uint32_t a) {
    asm volatile("ldmatrix.sync.aligned.m8n8.x4.shared.b16 {%0,%1,%2,%3}, [%4];"
        : "=r"(r[0]), "=r"(r[1]), "=r"(r[2]), "=r"(r[3]) : "r"(a));
}
__device__ __forceinline__ void mma_f16(float* d, const uint32_t* a, const uint32_t* b) {
    asm volatile("mma.sync.aligned.m16n8k16.row.col.f32.f16.f16.f32 "
        "{%0,%1,%2,%3},{%4,%5,%6,%7},{%8,%9},{%0,%1,%2,%3};"
        : "+f"(d[0]), "+f"(d[1]), "+f"(d[2]), "+f"(d[3])
        : "r"(a[0]), "r"(a[1]), "r"(a[2]), "r"(a[3]), "r"(b[0]), "r"(b[1]));
}

// smem tile: 128 rows x 32 fp16 cols, pitch 80B (64B data + 16B pad; 5r mod 8 permutation
// => conflict-free ldmatrix). K-chunk 32, double-buffered => 80KB => 2 CTAs/SM.
#define PITCH  80
#define TILEB  (128 * PITCH)     /* 10240 bytes per operand-limb tile */
#define STAGE  (4 * TILEB)       /* Ah | Al | Bh | Bl = 40960 */
#define SMEMSZ (2 * STAGE)       /* double buffered = 81920 */

// ---------------- split-fp16 HMMA GEMM ----------------
// C[M,Nv] = sum_seg A_seg[M,Kseg] * B[Nv,K]^T  (A row-major, B K-major [Nv,K])
// MODE 0: plain, 1-PRODUCT             MODE 1: __expf(2v-sq_i-sq_j), SYMMETRIC, 3-prod
// MODE 2: 2v - aux, 1-PRODUCT          MODE 3: relu(v + bias), 1-PRODUCT
// Writes fp32 to Cf, fp16 hi to Ch (+mirror for MODE 1), fp16 lo to Cl,
// transposed fp16 hi to Cth (each if non-null).
template<int MODE>
__global__ __launch_bounds__(256, 2) void gemm_mma(
    const bf16* A0h, const bf16* A0l, const bf16* A1h, const bf16* A1l,
    const bf16* A2h, const bf16* A2l,
    const bf16* Bh, const bf16* Bl,
    float* Cf, bf16* Ch, bf16* Cl, bf16* Cth,
    int M, int Nv, int K, int Kseg,
    long long sA, long long sB, long long sC, long long sT,
    const float* sqv, const float* aux, const float* bias)
{
    if (MODE == 1 && blockIdx.x > blockIdx.y) return;   // symmetric: skip upper-tri blocks

    extern __shared__ char sm[];
    uint32_t sb = smem_u32(sm);
    int tid = threadIdx.x, lane = tid & 31, w = tid >> 5;
    int wm = w & 1, wn = w >> 1;          // 2 x 4 warp grid, warp tile 64x32
    int b = blockIdx.z;
    int iBase = blockIdx.y * 128, jBase = blockIdx.x * 128;

    const bf16* a0h = A0h + (size_t)b * sA;
    const bf16* a0l = A0l + (size_t)b * sA;
    const bf16* a1h = A1h + (size_t)b * sA;
    const bf16* a1l = A1l + (size_t)b * sA;
    const bf16* a2h = A2h + (size_t)b * sA;
    const bf16* a2l = A2l + (size_t)b * sA;
    const bf16* bhp = Bh + (size_t)b * sB;
    const bf16* blp = Bl + (size_t)b * sB;

    float acc[4][4][4];
    #pragma unroll
    for (int i = 0; i < 4; i++)
        #pragma unroll
        for (int j = 0; j < 4; j++)
            #pragma unroll
            for (int k = 0; k < 4; k++) acc[i][j][k] = 0.f;

    int nk = (K + 31) >> 5;
    bool vec = ((K & 31) == 0) && ((Kseg & 31) == 0);
    int Kseg2 = 2 * Kseg;

    // ---- hoisted per-thread load invariants (32-bit; all offsets < 2^31) ----
    int rA  = tid >> 2;                       // row within group
    int ccA = (tid & 3) * 8;                  // k-element offset of this 16B chunk
    int aRow0 = (iBase + rA) * Kseg;
    int aRow1 = (iBase + rA + 64) * Kseg;
    int gn0 = jBase + rA, gn1 = jBase + rA + 64;
    int ok0 = (gn0 < Nv) ? 16 : 0, ok1 = (gn1 < Nv) ? 16 : 0;
    int bRow0 = (ok0 ? gn0 : 0) * K;
    int bRow1 = (ok1 ? gn1 : 0) * K;
    uint32_t so0 = (uint32_t)(rA * PITCH + (tid & 3) * 16);
    uint32_t so1 = so0 + (uint32_t)(64 * PITCH);

    auto load_vec = [&](int stg, int kc0) {
        uint32_t base = sb + stg * STAGE;
        int kg = kc0 + ccA;
        int seg = (kg >= Kseg) + (kg >= Kseg2);       // comparison-based, no IDIV
        const bf16* ph = (seg == 0) ? a0h : ((seg == 1) ? a1h : a2h);
        int kloc = kg - seg * Kseg;
        // group 0 (rows 0..63)
        cpa16(base + so0,             ph + (aRow0 + kloc), 16);
        cpa16(base + so0 + 2 * TILEB, bhp + (bRow0 + kg), ok0);
        // group 1 (rows 64..127)
        cpa16(base + so1,             ph + (aRow1 + kloc), 16);
        cpa16(base + so1 + 2 * TILEB, bhp + (bRow1 + kg), ok1);
        if (MODE == 1) {               // lo limbs only for the 3-product adjacency
            const bf16* pl = (seg == 0) ? a0l : ((seg == 1) ? a1l : a2l);
            cpa16(base + so0 + TILEB, pl + (aRow0 + kloc), 16);
            cpa16(base + so1 + TILEB, pl + (aRow1 + kloc), 16);
            cpa16(base + so0 + 3 * TILEB, blp + (bRow0 + kg), ok0);
            cpa16(base + so1 + 3 * TILEB, blp + (bRow1 + kg), ok1);
        }
    };

    auto compute = [&](int stg) {
        uint32_t base = sb + stg * STAGE;
        #pragma unroll
        for (int ks = 0; ks < 2; ks++) {
            int kk = ks * 16;
            uint32_t ah[4][4], al[4][4];
            #pragma unroll
            for (int i = 0; i < 4; i++) {
                int row = wm * 64 + i * 16 + (lane & 15);
                uint32_t ca = base + (uint32_t)(row * PITCH + ((lane >> 4) * 8 + kk) * 2);
                ldm4(ah[i], ca);
                if (MODE == 1) ldm4(al[i], ca + TILEB);
            }
            uint32_t bh[4][2], bl[4][2];
            #pragma unroll
            for (int jj = 0; jj < 2; jj++) {
                int rn = wn * 32 + jj * 16 + (lane & 7) + ((lane >> 4) & 1) * 8;
                uint32_t cb = base + 2 * TILEB +
                              (uint32_t)(rn * PITCH + (kk + ((lane >> 3) & 1) * 8) * 2);
                uint32_t t4[4];
                ldm4(t4, cb);
                bh[jj*2][0] = t4[0]; bh[jj*2][1] = t4[1];
                bh[jj*2+1][0] = t4[2]; bh[jj*2+1][1] = t4[3];
                if (MODE == 1) {
                    ldm4(t4, cb + TILEB);
                    bl[jj*2][0] = t4[0]; bl[jj*2][1] = t4[1];
                    bl[jj*2+1][0] = t4[2]; bl[jj*2+1][1] = t4[3];
                }
            }
            #pragma unroll
            for (int i = 0; i < 4; i++)
                #pragma unroll
                for (int j = 0; j < 4; j++) {
                    mma_f16(acc[i][j], ah[i], bh[j]);                   // hi*hi
                    if (MODE == 1) {
                        mma_f16(acc[i][j], ah[i], bl[j]);               // hi*lo
                        mma_f16(acc[i][j], al[i], bh[j]);               // lo*hi
                    }
                }
        }
    };

    if (vec) {
        // proven pipeline: load(i+1); commit; wait1; sync; compute(i); sync
        load_vec(0, 0); CP_COMMIT();
        for (int i = 0; i < nk; i++) {
            if (i + 1 < nk) { load_vec((i + 1) & 1, (i + 1) * 32); CP_COMMIT(); CP_WAIT1(); }
            else            { CP_WAIT0(); }
            __syncthreads();
            compute(i & 1);
            __syncthreads();
        }
    } else {
        // tiny-K path (layer 1 only: K=6 or K=18)
        for (int c = tid; c < STAGE / 16; c += 256) *(uint4*)(sm + (size_t)c * 16) = make_uint4(0,0,0,0);
        __syncthreads();
        for (int i = 0; i < nk; i++) {
            for (int idx = tid; idx < 128 * 32; idx += 256) {
                int r = idx >> 5, kc = idx & 31;
                int kg = i * 32 + kc;
                uint32_t so = (uint32_t)(r * PITCH + kc * 2);
                if (kg < K) {
                    int seg = (kg >= Kseg) + (kg >= Kseg2);
                    int kkk = kg - seg * Kseg;
                    const bf16* ph = (seg == 0) ? a0h : ((seg == 1) ? a1h : a2h);
                    *(bf16*)(sm + so) = ph[(size_t)(iBase + r) * Kseg + kkk];
                    if (MODE == 1) {
                        const bf16* pl = (seg == 0) ? a0l : ((seg == 1) ? a1l : a2l);
                        *(bf16*)(sm + so + TILEB) = pl[(size_t)(iBase + r) * Kseg + kkk];
                    }
                    int gn = jBase + r;
                    if (gn < Nv) {
                        *(bf16*)(sm + so + 2 * TILEB) = bhp[(size_t)gn * K + kg];
                        if (MODE == 1)
                            *(bf16*)(sm + so + 3 * TILEB) = blp[(size_t)gn * K + kg];
                    }
                }
            }
            __syncthreads();
            compute(0);
            __syncthreads();
            if (i + 1 < nk) {
                for (int c = tid; c < STAGE / 16; c += 256) *(uint4*)(sm + (size_t)c * 16) = make_uint4(0,0,0,0);
                __syncthreads();
            }
        }
    }

    // ---- epilogue (fused: fp32 / fp16 hi(+mirror) / fp16 lo / transposed hi) ----
    int g = lane >> 2, t = lane & 3;
    float* Cb  = Cf  ? Cf  + (size_t)b * sC : nullptr;
    bf16* Chb  = Ch  ? Ch  + (size_t)b * sC : nullptr;
    bf16* Clb  = Cl  ? Cl  + (size_t)b * sC : nullptr;
    bf16* Cthb = Cth ? Cth + (size_t)b * sT : nullptr;
    bool mirror = (MODE == 1) && (blockIdx.x < blockIdx.y);
    #pragma unroll
    for (int i = 0; i < 4; i++) {
        #pragma unroll
        for (int rr = 0; rr < 2; rr++) {
            int row = iBase + wm * 64 + i * 16 + g + rr * 8;   // M is multiple of 128
            float sqi = (MODE == 1) ? sqv[b * N_ + row] : 0.f;
            #pragma unroll
            for (int j = 0; j < 4; j++) {
                int col = jBase + wn * 32 + j * 8 + 2 * t;
                #pragma unroll
                for (int cc = 0; cc < 2; cc++) {
                    int c2 = col + cc;
                    if (c2 < Nv) {
                        float v = acc[i][j][rr * 2 + cc];
                        if (MODE == 1)      v = __expf(2.f * v - sqi - sqv[b * N_ + c2]);
                        else if (MODE == 2) v = 2.f * v - aux[(size_t)b * sC + (size_t)row * Nv + c2];
                        else if (MODE == 3) v = fmaxf(v + bias[c2], 0.f);
                        size_t o = (size_t)row * Nv + c2;
                        if (Cb) Cb[o] = v;
                        if (Chb) {
                            bf16 h = f2l(v);
                            Chb[o] = h;
                            if (mirror) Chb[(size_t)c2 * Nv + row] = h;   // symmetric mirror
                            if (Clb) Clb[o] = f2l(v - l2f(h));
                            if (Cthb) Cthb[(size_t)c2 * N_ + row] = h;    // fused transpose
                        }
                    }
                }
            }
        }
    }
}

// ---------------- conversion / elementwise kernels ----------------
__global__ void split_fp32(const float* __restrict__ X, bf16* __restrict__ H, bf16* __restrict__ L, size_t n) {
    size_t i = ((size_t)blockIdx.x * 256 + threadIdx.x) * 4;
    if (i >= n) return;
    float4 v = *(const float4*)(X + i);
    bf16 hv[4], lv[4];
    float vv[4] = {v.x, v.y, v.z, v.w};
    #pragma unroll
    for (int k = 0; k < 4; k++) {
        bf16 h = f2l(vv[k]);
        hv[k] = h;
        lv[k] = f2l(vv[k] - l2f(h));
    }
    *(uint2*)(H + i) = *(uint2*)hv;
    *(uint2*)(L + i) = *(uint2*)lv;
}

// transpose, hi limb only (L-x gemms are 1-product)
__global__ void transpose_split(const float* __restrict__ X, bf16* __restrict__ Th, int F) {
    __shared__ float tile[32][33];
    int b = blockIdx.z;
    int n0 = blockIdx.x * 32, f0 = blockIdx.y * 32;
    const float* Xb = X + (size_t)b * N_ * F;
    #pragma unroll
    for (int i = 0; i < 32; i += 8) {
        int nn = n0 + threadIdx.y + i, ff = f0 + threadIdx.x;
        if (ff < F) tile[threadIdx.y + i][threadIdx.x] = Xb[(size_t)nn * F + ff];
    }
    __syncthreads();
    bf16* Thb = Th + (size_t)b * F * N_;
    #pragma unroll
    for (int i = 0; i < 32; i += 8) {
        int ff = f0 + threadIdx.y + i, nn = n0 + threadIdx.x;
        if (ff < F) Thb[(size_t)ff * N_ + nn] = f2l(tile[threadIdx.x][threadIdx.y + i]);
    }
}

// weights: hi limb only (feature gemm is single-product)
__global__ void wtrans(const float* __restrict__ W, bf16* __restrict__ Th, int Fi, int Fo) {
    int kg = blockIdx.x * 32 + threadIdx.x;
    int o  = blockIdx.y * 8 + threadIdx.y;
    int Kt = 3 * Fi;
    if (kg < Kt && o < Fo) {
        int seg = (kg >= Fi) + (kg >= 2 * Fi);
        int kc = kg - seg * Fi;
        Th[(size_t)o * Kt + kg] = f2l(W[((size_t)seg * Fi + kc) * Fo + o]);
    }
}

__global__ void sqnorm(const float* __restrict__ X, float* __restrict__ sq, int F) {
    int row = blockIdx.x * 8 + threadIdx.y;
    const float* r = X + (size_t)row * F;
    float s = 0.f;
    for (int f = threadIdx.x; f < F; f += 32) { float v = r[f]; s += v * v; }
    #pragma unroll
    for (int o = 16; o; o >>= 1) s += __shfl_xor_sync(0xffffffffu, s, o);
    if (threadIdx.x == 0) sq[row] = s;
}

// row degree over fp16 adjacency
__global__ void rowdeg(const bf16* __restrict__ A, float* __restrict__ dis) {
    int row = blockIdx.x * 8 + threadIdx.y;
    const __half2* r = (const __half2*)(A + (size_t)row * N_);
    float s = 0.f;
    for (int m = threadIdx.x; m < N_ / 2; m += 32) {
        float2 v = __half22float2(r[m]);
        s += v.x + v.y;
    }
    #pragma unroll
    for (int o = 16; o; o >>= 1) s += __shfl_xor_sync(0xffffffffu, s, o);
    if (threadIdx.x == 0) dis[row] = rsqrtf(s);
}

// L = I - dis_i*A*dis_j  (fp16 in, fp16 out)
__global__ void makeL_split(const bf16* __restrict__ A, const float* __restrict__ dis,
                            bf16* __restrict__ Lh) {
    size_t idx = ((size_t)blockIdx.x * 256 + threadIdx.x) * 4;
    int j0 = (int)(idx & (N_ - 1));
    size_t t = idx >> 10;
    int i = (int)(t & (N_ - 1));
    int b = (int)(t >> 10);
    float di = dis[b * N_ + i];
    uint2 araw = *(const uint2*)(A + idx);
    bf16 av[4];
    *(uint2*)av = araw;
    bf16 hv[4];
    #pragma unroll
    for (int k = 0; k < 4; k++) {
        float v = -di * dis[b * N_ + j0 + k] * l2f(av[k]);
        if (i == j0 + k) v += 1.f;
        hv[k] = f2l(v);
    }
    *(uint2*)(Lh + idx) = *(uint2*)hv;
}

__global__ void maxpool(const float* __restrict__ H, float* __restrict__ out) {
    int f = blockIdx.x * 256 + threadIdx.x;
    int b = blockIdx.y;
    const float* base = H + (size_t)b * N_ * 1024 + f;
    float m = -1e30f;
    for (int n = 0; n < N_; n++) m = fmaxf(m, base[(size_t)n * 1024]);
    out[b * 1024 + f] = m;
}

__global__ void fckernel(const float* __restrict__ in, const float* __restrict__ W,
                         const float* __restrict__ bias, float* __restrict__ out,
                         int K, int Nout, int dorelu) {
    __shared__ float s[1024];
    int b = blockIdx.x;
    for (int i = threadIdx.x; i < K; i += blockDim.x) s[i] = in[(size_t)b * K + i];
    __syncthreads();
    for (int j = threadIdx.x; j < Nout; j += blockDim.x) {
        float acc = bias[j];
        for (int i = 0; i < K; i++) acc = fmaf(s[i], W[(size_t)i * Nout + j], acc);
        if (dorelu) acc = fmaxf(acc, 0.f);
        out[(size_t)b * Nout + j] = acc;
    }
}

// ---------------- host orchestration ----------------
struct Ptrs {
    float *sq, *dis;
    bf16 *A, *Th, *T2h, *Lh, *x1h, *x2h, *Wh;
};

// inH/inL: split of layer input P (already populated). outH/outL: split of H for next layer (may be null).
static void conv_layer(const float* P, bf16* inH, bf16* inL, int Fi, int Fo,
                       const float* W, const float* bias,
                       float* H, bf16* outH, bf16* outL, const Ptrs& p)
{
    dim3 tb32(32, 8);

    transpose_split<<<dim3(32, (Fi + 31) / 32, B_), tb32>>>(P, p.Th, Fi);
    sqnorm<<<B_ * N_ / 8, tb32>>>(P, p.sq, Fi);

    // adjacency: A = exp(2*X*X^T - sq_i - sq_j)  — symmetric, 3-product, fp16 output+mirror
    gemm_mma<1><<<dim3(8, 8, B_), 256, SMEMSZ>>>(
        inH, inL, inH, inL, inH, inL, inH, inL,
        nullptr, p.A, nullptr, nullptr,
        N_, N_, Fi, Fi, (long long)N_ * Fi, (long long)N_ * Fi, (long long)N_ * N_, 0,
        p.sq, nullptr, nullptr);

    rowdeg<<<B_ * N_ / 8, tb32>>>(p.A, p.dis);
    makeL_split<<<(unsigned)((size_t)B_ * N_ * N_ / 1024), 256>>>(p.A, p.dis, p.Lh);

    // x1 = L @ x0 : 1-product; hi split + fused transposed hi (x2 gemm B)
    gemm_mma<0><<<dim3((Fi + 127) / 128, 8, B_), 256, SMEMSZ>>>(
        p.Lh, p.Lh, p.Lh, p.Lh, p.Lh, p.Lh, p.Th, p.Th,
        nullptr, p.x1h, nullptr, p.T2h,
        N_, Fi, N_, N_, (long long)N_ * N_, (long long)Fi * N_, (long long)N_ * Fi, (long long)Fi * N_,
        nullptr, nullptr, nullptr);

    // x2 = 2 L @ x1 - x0 : 1-product; hi split only
    gemm_mma<2><<<dim3((Fi + 127) / 128, 8, B_), 256, SMEMSZ>>>(
        p.Lh, p.Lh, p.Lh, p.Lh, p.Lh, p.Lh, p.T2h, p.T2h,
        nullptr, p.x2h, nullptr, nullptr,
        N_, Fi, N_, N_, (long long)N_ * N_, (long long)Fi * N_, (long long)N_ * Fi, 0,
        nullptr, P, nullptr);

    wtrans<<<dim3((3 * Fi + 31) / 32, (Fo + 7) / 8), tb32>>>(W, p.Wh, Fi, Fo);

    // H = relu(x0 W0 + x1 W1 + x2 W2 + b); 1-product; emits next layer's split (both limbs)
    gemm_mma<3><<<dim3((Fo + 127) / 128, B_ * N_ / 128, 1), 256, SMEMSZ>>>(
        inH, inH, p.x1h, p.x1h, p.x2h, p.x2h, p.Wh, p.Wh,
        H, outH, outL, nullptr,
        B_ * N_, Fo, 3 * Fi, Fi, 0, 0, 0, 0,
        nullptr, nullptr, bias);
}

extern "C" void kernel_launch(void* const* d_in, const int* in_sizes, int n_in,
                              void* d_out, int out_size) {
    (void)in_sizes; (void)n_in; (void)out_size;
    const float* x     = (const float*)d_in[0];
    const float* W1    = (const float*)d_in[1];
    const float* b1    = (const float*)d_in[2];
    const float* W2    = (const float*)d_in[3];
    const float* b2    = (const float*)d_in[4];
    const float* W3    = (const float*)d_in[5];
    const float* b3    = (const float*)d_in[6];
    const float* fc1_w = (const float*)d_in[7];
    const float* fc1_b = (const float*)d_in[8];
    const float* fc2_w = (const float*)d_in[9];
    const float* fc2_b = (const float*)d_in[10];
    const float* fc3_w = (const float*)d_in[11];
    const float* fc3_b = (const float*)d_in[12];
    float* out = (float*)d_out;

    cudaFuncSetAttribute(gemm_mma<0>, cudaFuncAttributeMaxDynamicSharedMemorySize, SMEMSZ);
    cudaFuncSetAttribute(gemm_mma<1>, cudaFuncAttributeMaxDynamicSharedMemorySize, SMEMSZ);
    cudaFuncSetAttribute(gemm_mma<2>, cudaFuncAttributeMaxDynamicSharedMemorySize, SMEMSZ);
    cudaFuncSetAttribute(gemm_mma<3>, cudaFuncAttributeMaxDynamicSharedMemorySize, SMEMSZ);

    Ptrs p;
    bf16 *Xh, *Xl, *Yh, *Yl;
    float *H1, *H2, *H3, *pool, *f1, *f2;
    cudaGetSymbolAddress((void**)&p.A,   g_A);
    cudaGetSymbolAddress((void**)&p.sq,  g_sq);
    cudaGetSymbolAddress((void**)&p.dis, g_dis);
    cudaGetSymbolAddress((void**)&Xh,    g_Xh);
    cudaGetSymbolAddress((void**)&Xl,    g_Xl);
    cudaGetSymbolAddress((void**)&Yh,    g_Yh);
    cudaGetSymbolAddress((void**)&Yl,    g_Yl);
    cudaGetSymbolAddress((void**)&p.Th,  g_Th);
    cudaGetSymbolAddress((void**)&p.T2h, g_T2h);
    cudaGetSymbolAddress((void**)&p.Lh,  g_Lh);
    cudaGetSymbolAddress((void**)&p.x1h, g_x1h);
    cudaGetSymbolAddress((void**)&p.x2h, g_x2h);
    cudaGetSymbolAddress((void**)&p.Wh,  g_Wh);
    cudaGetSymbolAddress((void**)&H1,    g_H1);
    cudaGetSymbolAddress((void**)&H2,    g_H2);
    cudaGetSymbolAddress((void**)&H3,    g_H3);
    cudaGetSymbolAddress((void**)&pool,  g_pool);
    cudaGetSymbolAddress((void**)&f1,    g_f1);
    cudaGetSymbolAddress((void**)&f2,    g_f2);

    // layer 1: split the raw input, H1 split -> Y
    split_fp32<<<(unsigned)(((size_t)B_ * N_ * 6 + 1023) / 1024), 256>>>(x, Xh, Xl, (size_t)B_ * N_ * 6);
    conv_layer(x,  Xh, Xl, 6,   128,  W1, b1, H1, Yh, Yl, p);
    // layer 2: input split = Y, H2 split -> X (ping-pong)
    conv_layer(H1, Yh, Yl, 128, 512,  W2, b2, H2, Xh, Xl, p);
    // layer 3: input split = X, no H split needed
    conv_layer(H2, Xh, Xl, 512, 1024, W3, b3, H3, nullptr, nullptr, p);

    maxpool<<<dim3(4, B_), 256>>>(H3, pool);
    fckernel<<<B_, 256>>>(pool, fc1_w, fc1_b, f1, 1024, 512, 1);
    fckernel<<<B_, 256>>>(f1,   fc2_w, fc2_b, f2, 512, 128, 1);
    fckernel<<<B_, 256>>>(f2,   fc3_w, fc3_b, out, 128, 40, 0);
}